// round 1
// baseline (speedup 1.0000x reference)
#include <cuda_runtime.h>
#include <cfloat>
#include <cstdint>

// Problem constants (fixed by the reference)
#define B_   16
#define N_   4096
#define D_   1024
#define H_   512
#define O_   4096
#define KSEL 200
#define TOK  (B_ * N_)   // 65536 tokens

// Scratch (no cudaMalloc allowed)
__device__ float g_scores[TOK];
__device__ int   g_topk[B_ * KSEL];

// ---------------- f32x2 packed-FMA helpers (Blackwell FFMA2 path) ----------------
__device__ __forceinline__ unsigned long long pack2(float lo, float hi) {
    unsigned long long r;
    asm("mov.b64 %0, {%1, %2};" : "=l"(r) : "f"(lo), "f"(hi));
    return r;
}
__device__ __forceinline__ void unpack2(unsigned long long v, float& lo, float& hi) {
    asm("mov.b64 {%0, %1}, %2;" : "=f"(lo), "=f"(hi) : "l"(v));
}
__device__ __forceinline__ void fma2(unsigned long long& c, unsigned long long a,
                                     unsigned long long b) {
    asm("fma.rn.f32x2 %0, %1, %2, %0;" : "+l"(c) : "l"(a), "l"(b));
}

__device__ __forceinline__ float gelu_exact(float v) {
    return 0.5f * v * (1.0f + erff(v * 0.70710678118654752440f));
}

// =====================================================================
// Kernel 1: fused score = GELU(x @ W1^T + b1) . W2   -> g_scores[65536]
// 128 tokens x 128 h per tile, 4 h-chunks per block, BK=16, 256 thr, 8x8/thr
// =====================================================================
__global__ void __launch_bounds__(256, 2)
score_kernel(const float* __restrict__ x, const float* __restrict__ W1,
             const float* __restrict__ b1, const float* __restrict__ W2) {
    __shared__ __align__(16) float As[16][128];
    __shared__ __align__(16) float Bs[16][128];
    __shared__ float sB1[H_];
    __shared__ float sW2[H_];
    __shared__ float red[128][17];

    const int t    = threadIdx.x;
    const int m0   = blockIdx.x * 128;      // token tile base (flat over B*N)
    const int tx   = t & 15;
    const int ty   = t >> 4;
    const int rowA = t >> 1;                // 0..127
    const int colA = (t & 1) * 8;           // 0 or 8

    for (int i = t; i < H_; i += 256) { sB1[i] = b1[i]; sW2[i] = W2[i]; }

    float sp[8];
#pragma unroll
    for (int i = 0; i < 8; i++) sp[i] = 0.0f;

    for (int hc = 0; hc < 4; hc++) {
        unsigned long long acc[8][4];
#pragma unroll
        for (int i = 0; i < 8; i++)
#pragma unroll
            for (int jp = 0; jp < 4; jp++) acc[i][jp] = pack2(0.0f, 0.0f);

        const float* Arow = x  + (size_t)(m0 + rowA) * D_ + colA;
        const float* Brow = W1 + (size_t)(hc * 128 + rowA) * D_ + colA;

        for (int k0 = 0; k0 < D_; k0 += 16) {
            float4 a0 = *(const float4*)(Arow + k0);
            float4 a1 = *(const float4*)(Arow + k0 + 4);
            float4 w0 = *(const float4*)(Brow + k0);
            float4 w1 = *(const float4*)(Brow + k0 + 4);
            __syncthreads();   // previous tile fully consumed
            As[colA + 0][rowA] = a0.x; As[colA + 1][rowA] = a0.y;
            As[colA + 2][rowA] = a0.z; As[colA + 3][rowA] = a0.w;
            As[colA + 4][rowA] = a1.x; As[colA + 5][rowA] = a1.y;
            As[colA + 6][rowA] = a1.z; As[colA + 7][rowA] = a1.w;
            Bs[colA + 0][rowA] = w0.x; Bs[colA + 1][rowA] = w0.y;
            Bs[colA + 2][rowA] = w0.z; Bs[colA + 3][rowA] = w0.w;
            Bs[colA + 4][rowA] = w1.x; Bs[colA + 5][rowA] = w1.y;
            Bs[colA + 6][rowA] = w1.z; Bs[colA + 7][rowA] = w1.w;
            __syncthreads();

#pragma unroll
            for (int kk = 0; kk < 16; kk++) {
                float4 av0 = *(const float4*)&As[kk][ty * 8];
                float4 av1 = *(const float4*)&As[kk][ty * 8 + 4];
                ulonglong2 bv0 = *(const ulonglong2*)&Bs[kk][tx * 8];
                ulonglong2 bv1 = *(const ulonglong2*)&Bs[kk][tx * 8 + 4];
                unsigned long long br[4] = {bv0.x, bv0.y, bv1.x, bv1.y};
                float ar[8] = {av0.x, av0.y, av0.z, av0.w,
                               av1.x, av1.y, av1.z, av1.w};
#pragma unroll
                for (int i = 0; i < 8; i++) {
                    unsigned long long aa = pack2(ar[i], ar[i]);
#pragma unroll
                    for (int jp = 0; jp < 4; jp++) fma2(acc[i][jp], aa, br[jp]);
                }
            }
        }

        // epilogue for this h-chunk: +b1, exact GELU, dot with W2
#pragma unroll
        for (int i = 0; i < 8; i++) {
            float rs = 0.0f;
#pragma unroll
            for (int jp = 0; jp < 4; jp++) {
                float c0, c1;
                unpack2(acc[i][jp], c0, c1);
                int h = hc * 128 + tx * 8 + jp * 2;
                rs += gelu_exact(c0 + sB1[h])     * sW2[h];
                rs += gelu_exact(c1 + sB1[h + 1]) * sW2[h + 1];
            }
            sp[i] += rs;
        }
    }

    __syncthreads();
#pragma unroll
    for (int i = 0; i < 8; i++) red[ty * 8 + i][tx] = sp[i];
    __syncthreads();
    if (t < 128) {
        float s = 0.0f;
#pragma unroll
        for (int j = 0; j < 16; j++) s += red[t][j];
        g_scores[m0 + t] = s;   // b2 is a constant shift -> irrelevant for topk
    }
}

// =====================================================================
// Kernel 2: per-batch top-200 (descending value, ascending index on ties)
// =====================================================================
__global__ void __launch_bounds__(256)
topk_kernel() {
    __shared__ float s[N_];
    __shared__ float wv[8];
    __shared__ int   wi[8];
    const int b = blockIdx.x;
    const int t = threadIdx.x;

    for (int i = t; i < N_; i += 256) s[i] = g_scores[b * N_ + i];
    __syncthreads();

    for (int it = 0; it < KSEL; it++) {
        float bv = -FLT_MAX;
        int   bi = 0x7fffffff;
        for (int i = t; i < N_; i += 256) {
            float v = s[i];
            if (v > bv || (v == bv && i < bi)) { bv = v; bi = i; }
        }
#pragma unroll
        for (int off = 16; off > 0; off >>= 1) {
            float ov = __shfl_down_sync(0xffffffffu, bv, off);
            int   oi = __shfl_down_sync(0xffffffffu, bi, off);
            if (ov > bv || (ov == bv && oi < bi)) { bv = ov; bi = oi; }
        }
        if ((t & 31) == 0) { wv[t >> 5] = bv; wi[t >> 5] = bi; }
        __syncthreads();
        if (t == 0) {
            for (int w = 1; w < 8; w++) {
                if (wv[w] > bv || (wv[w] == bv && wi[w] < bi)) { bv = wv[w]; bi = wi[w]; }
            }
            g_topk[b * KSEL + it] = bi;
            s[bi] = -FLT_MAX;
        }
        __syncthreads();
    }
}

// =====================================================================
// Kernel 3: out[b,k,:] = x[b, topk[b,k], :] @ Wp^T + bp
// grid: (O/128, ceil(200/128)=2, B), same FFMA2 tiling
// =====================================================================
__global__ void __launch_bounds__(256, 2)
proj_kernel(const float* __restrict__ x, const float* __restrict__ Wp,
            const float* __restrict__ bp, float* __restrict__ out) {
    __shared__ __align__(16) float As[16][128];
    __shared__ __align__(16) float Bs[16][128];
    __shared__ int rowidx[128];

    const int t    = threadIdx.x;
    const int b    = blockIdx.z;
    const int mt   = blockIdx.y;            // 0..1 (row tile)
    const int o0   = blockIdx.x * 128;
    const int tx   = t & 15;
    const int ty   = t >> 4;
    const int rowA = t >> 1;
    const int colA = (t & 1) * 8;

    if (t < 128) {
        int m = mt * 128 + t;
        rowidx[t] = (m < KSEL) ? g_topk[b * KSEL + m] : 0;
    }
    __syncthreads();

    const int tokenA = rowidx[rowA];
    const float* Arow = x  + ((size_t)b * N_ + tokenA) * D_ + colA;
    const float* Brow = Wp + (size_t)(o0 + rowA) * D_ + colA;

    unsigned long long acc[8][4];
#pragma unroll
    for (int i = 0; i < 8; i++)
#pragma unroll
        for (int jp = 0; jp < 4; jp++) acc[i][jp] = pack2(0.0f, 0.0f);

    for (int k0 = 0; k0 < D_; k0 += 16) {
        float4 a0 = *(const float4*)(Arow + k0);
        float4 a1 = *(const float4*)(Arow + k0 + 4);
        float4 w0 = *(const float4*)(Brow + k0);
        float4 w1 = *(const float4*)(Brow + k0 + 4);
        __syncthreads();
        As[colA + 0][rowA] = a0.x; As[colA + 1][rowA] = a0.y;
        As[colA + 2][rowA] = a0.z; As[colA + 3][rowA] = a0.w;
        As[colA + 4][rowA] = a1.x; As[colA + 5][rowA] = a1.y;
        As[colA + 6][rowA] = a1.z; As[colA + 7][rowA] = a1.w;
        Bs[colA + 0][rowA] = w0.x; Bs[colA + 1][rowA] = w0.y;
        Bs[colA + 2][rowA] = w0.z; Bs[colA + 3][rowA] = w0.w;
        Bs[colA + 4][rowA] = w1.x; Bs[colA + 5][rowA] = w1.y;
        Bs[colA + 6][rowA] = w1.z; Bs[colA + 7][rowA] = w1.w;
        __syncthreads();

#pragma unroll
        for (int kk = 0; kk < 16; kk++) {
            float4 av0 = *(const float4*)&As[kk][ty * 8];
            float4 av1 = *(const float4*)&As[kk][ty * 8 + 4];
            ulonglong2 bv0 = *(const ulonglong2*)&Bs[kk][tx * 8];
            ulonglong2 bv1 = *(const ulonglong2*)&Bs[kk][tx * 8 + 4];
            unsigned long long br[4] = {bv0.x, bv0.y, bv1.x, bv1.y};
            float ar[8] = {av0.x, av0.y, av0.z, av0.w,
                           av1.x, av1.y, av1.z, av1.w};
#pragma unroll
            for (int i = 0; i < 8; i++) {
                unsigned long long aa = pack2(ar[i], ar[i]);
#pragma unroll
                for (int jp = 0; jp < 4; jp++) fma2(acc[i][jp], aa, br[jp]);
            }
        }
    }

#pragma unroll
    for (int i = 0; i < 8; i++) {
        int m = mt * 128 + ty * 8 + i;
        if (m < KSEL) {
            float* orow = out + ((size_t)b * KSEL + m) * O_ + o0 + tx * 8;
#pragma unroll
            for (int jp = 0; jp < 4; jp++) {
                float c0, c1;
                unpack2(acc[i][jp], c0, c1);
                int o = o0 + tx * 8 + jp * 2;
                float2 v = make_float2(c0 + bp[o], c1 + bp[o + 1]);
                *(float2*)&orow[jp * 2] = v;
            }
        }
    }
}

// =====================================================================
// Entry point
// =====================================================================
extern "C" void kernel_launch(void* const* d_in, const int* in_sizes, int n_in,
                              void* d_out, int out_size) {
    (void)in_sizes; (void)n_in; (void)out_size;
    const float* x  = (const float*)d_in[0];
    const float* W1 = (const float*)d_in[1];
    const float* b1 = (const float*)d_in[2];
    const float* W2 = (const float*)d_in[3];
    // d_in[4] = b2: constant shift on scores, irrelevant to topk -> unused
    const float* Wp = (const float*)d_in[5];
    const float* bp = (const float*)d_in[6];
    float* out = (float*)d_out;

    score_kernel<<<TOK / 128, 256>>>(x, W1, b1, W2);
    topk_kernel<<<B_, 256>>>();
    proj_kernel<<<dim3(O_ / 128, (KSEL + 127) / 128, B_), 256>>>(x, Wp, bp, out);
}

// round 2
// speedup vs baseline: 1.0011x; 1.0011x over previous
#include <cuda_runtime.h>
#include <cfloat>
#include <cstdint>

// Problem constants (fixed by the reference)
#define B_   16
#define N_   4096
#define D_   1024
#define H_   512
#define O_   4096
#define KSEL 200
#define TOK  (B_ * N_)   // 65536 tokens

// Scratch (no cudaMalloc allowed)
__device__ float g_scores[TOK];
__device__ int   g_topk[B_ * KSEL];

// ---------------- f32x2 packed-FMA helpers (Blackwell FFMA2 path) ----------------
__device__ __forceinline__ unsigned long long pack2(float lo, float hi) {
    unsigned long long r;
    asm("mov.b64 %0, {%1, %2};" : "=l"(r) : "f"(lo), "f"(hi));
    return r;
}
__device__ __forceinline__ void unpack2(unsigned long long v, float& lo, float& hi) {
    asm("mov.b64 {%0, %1}, %2;" : "=f"(lo), "=f"(hi) : "l"(v));
}
__device__ __forceinline__ void fma2(unsigned long long& c, unsigned long long a,
                                     unsigned long long b) {
    asm("fma.rn.f32x2 %0, %1, %2, %0;" : "+l"(c) : "l"(a), "l"(b));
}

__device__ __forceinline__ float gelu_exact(float v) {
    return 0.5f * v * (1.0f + erff(v * 0.70710678118654752440f));
}

// =====================================================================
// Kernel 1: fused score = GELU(x @ W1^T + b1) . W2   -> g_scores[65536]
// 128 tokens x 128 h per tile, 4 h-chunks per block, BK=16, 256 thr, 8x8/thr
// =====================================================================
__global__ void __launch_bounds__(256, 2)
score_kernel(const float* __restrict__ x, const float* __restrict__ W1,
             const float* __restrict__ b1, const float* __restrict__ W2) {
    __shared__ __align__(16) float As[16][128];
    __shared__ __align__(16) float Bs[16][128];
    __shared__ float sB1[H_];
    __shared__ float sW2[H_];
    __shared__ float red[128][17];

    const int t    = threadIdx.x;
    const int m0   = blockIdx.x * 128;      // token tile base (flat over B*N)
    const int tx   = t & 15;
    const int ty   = t >> 4;
    const int rowA = t >> 1;                // 0..127
    const int colA = (t & 1) * 8;           // 0 or 8

    for (int i = t; i < H_; i += 256) { sB1[i] = b1[i]; sW2[i] = W2[i]; }

    float sp[8];
#pragma unroll
    for (int i = 0; i < 8; i++) sp[i] = 0.0f;

    for (int hc = 0; hc < 4; hc++) {
        unsigned long long acc[8][4];
#pragma unroll
        for (int i = 0; i < 8; i++)
#pragma unroll
            for (int jp = 0; jp < 4; jp++) acc[i][jp] = pack2(0.0f, 0.0f);

        const float* Arow = x  + (size_t)(m0 + rowA) * D_ + colA;
        const float* Brow = W1 + (size_t)(hc * 128 + rowA) * D_ + colA;

        for (int k0 = 0; k0 < D_; k0 += 16) {
            float4 a0 = *(const float4*)(Arow + k0);
            float4 a1 = *(const float4*)(Arow + k0 + 4);
            float4 w0 = *(const float4*)(Brow + k0);
            float4 w1 = *(const float4*)(Brow + k0 + 4);
            __syncthreads();   // previous tile fully consumed
            As[colA + 0][rowA] = a0.x; As[colA + 1][rowA] = a0.y;
            As[colA + 2][rowA] = a0.z; As[colA + 3][rowA] = a0.w;
            As[colA + 4][rowA] = a1.x; As[colA + 5][rowA] = a1.y;
            As[colA + 6][rowA] = a1.z; As[colA + 7][rowA] = a1.w;
            Bs[colA + 0][rowA] = w0.x; Bs[colA + 1][rowA] = w0.y;
            Bs[colA + 2][rowA] = w0.z; Bs[colA + 3][rowA] = w0.w;
            Bs[colA + 4][rowA] = w1.x; Bs[colA + 5][rowA] = w1.y;
            Bs[colA + 6][rowA] = w1.z; Bs[colA + 7][rowA] = w1.w;
            __syncthreads();

#pragma unroll
            for (int kk = 0; kk < 16; kk++) {
                float4 av0 = *(const float4*)&As[kk][ty * 8];
                float4 av1 = *(const float4*)&As[kk][ty * 8 + 4];
                ulonglong2 bv0 = *(const ulonglong2*)&Bs[kk][tx * 8];
                ulonglong2 bv1 = *(const ulonglong2*)&Bs[kk][tx * 8 + 4];
                unsigned long long br[4] = {bv0.x, bv0.y, bv1.x, bv1.y};
                float ar[8] = {av0.x, av0.y, av0.z, av0.w,
                               av1.x, av1.y, av1.z, av1.w};
#pragma unroll
                for (int i = 0; i < 8; i++) {
                    unsigned long long aa = pack2(ar[i], ar[i]);
#pragma unroll
                    for (int jp = 0; jp < 4; jp++) fma2(acc[i][jp], aa, br[jp]);
                }
            }
        }

        // epilogue for this h-chunk: +b1, exact GELU, dot with W2
#pragma unroll
        for (int i = 0; i < 8; i++) {
            float rs = 0.0f;
#pragma unroll
            for (int jp = 0; jp < 4; jp++) {
                float c0, c1;
                unpack2(acc[i][jp], c0, c1);
                int h = hc * 128 + tx * 8 + jp * 2;
                rs += gelu_exact(c0 + sB1[h])     * sW2[h];
                rs += gelu_exact(c1 + sB1[h + 1]) * sW2[h + 1];
            }
            sp[i] += rs;
        }
    }

    __syncthreads();
#pragma unroll
    for (int i = 0; i < 8; i++) red[ty * 8 + i][tx] = sp[i];
    __syncthreads();
    if (t < 128) {
        float s = 0.0f;
#pragma unroll
        for (int j = 0; j < 16; j++) s += red[t][j];
        g_scores[m0 + t] = s;   // b2 is a constant shift -> irrelevant for topk
    }
}

// =====================================================================
// Kernel 2: per-batch top-200 (descending value, ascending index on ties)
// =====================================================================
__global__ void __launch_bounds__(256)
topk_kernel() {
    __shared__ float s[N_];
    __shared__ float wv[8];
    __shared__ int   wi[8];
    const int b = blockIdx.x;
    const int t = threadIdx.x;

    for (int i = t; i < N_; i += 256) s[i] = g_scores[b * N_ + i];
    __syncthreads();

    for (int it = 0; it < KSEL; it++) {
        float bv = -FLT_MAX;
        int   bi = 0x7fffffff;
        for (int i = t; i < N_; i += 256) {
            float v = s[i];
            if (v > bv || (v == bv && i < bi)) { bv = v; bi = i; }
        }
#pragma unroll
        for (int off = 16; off > 0; off >>= 1) {
            float ov = __shfl_down_sync(0xffffffffu, bv, off);
            int   oi = __shfl_down_sync(0xffffffffu, bi, off);
            if (ov > bv || (ov == bv && oi < bi)) { bv = ov; bi = oi; }
        }
        if ((t & 31) == 0) { wv[t >> 5] = bv; wi[t >> 5] = bi; }
        __syncthreads();
        if (t == 0) {
            for (int w = 1; w < 8; w++) {
                if (wv[w] > bv || (wv[w] == bv && wi[w] < bi)) { bv = wv[w]; bi = wi[w]; }
            }
            g_topk[b * KSEL + it] = bi;
            s[bi] = -FLT_MAX;
        }
        __syncthreads();
    }
}

// =====================================================================
// Kernel 3: out[b,k,:] = x[b, topk[b,k], :] @ Wp^T + bp
// grid: (O/128, ceil(200/128)=2, B), same FFMA2 tiling
// =====================================================================
__global__ void __launch_bounds__(256, 2)
proj_kernel(const float* __restrict__ x, const float* __restrict__ Wp,
            const float* __restrict__ bp, float* __restrict__ out) {
    __shared__ __align__(16) float As[16][128];
    __shared__ __align__(16) float Bs[16][128];
    __shared__ int rowidx[128];

    const int t    = threadIdx.x;
    const int b    = blockIdx.z;
    const int mt   = blockIdx.y;            // 0..1 (row tile)
    const int o0   = blockIdx.x * 128;
    const int tx   = t & 15;
    const int ty   = t >> 4;
    const int rowA = t >> 1;
    const int colA = (t & 1) * 8;

    if (t < 128) {
        int m = mt * 128 + t;
        rowidx[t] = (m < KSEL) ? g_topk[b * KSEL + m] : 0;
    }
    __syncthreads();

    const int tokenA = rowidx[rowA];
    const float* Arow = x  + ((size_t)b * N_ + tokenA) * D_ + colA;
    const float* Brow = Wp + (size_t)(o0 + rowA) * D_ + colA;

    unsigned long long acc[8][4];
#pragma unroll
    for (int i = 0; i < 8; i++)
#pragma unroll
        for (int jp = 0; jp < 4; jp++) acc[i][jp] = pack2(0.0f, 0.0f);

    for (int k0 = 0; k0 < D_; k0 += 16) {
        float4 a0 = *(const float4*)(Arow + k0);
        float4 a1 = *(const float4*)(Arow + k0 + 4);
        float4 w0 = *(const float4*)(Brow + k0);
        float4 w1 = *(const float4*)(Brow + k0 + 4);
        __syncthreads();
        As[colA + 0][rowA] = a0.x; As[colA + 1][rowA] = a0.y;
        As[colA + 2][rowA] = a0.z; As[colA + 3][rowA] = a0.w;
        As[colA + 4][rowA] = a1.x; As[colA + 5][rowA] = a1.y;
        As[colA + 6][rowA] = a1.z; As[colA + 7][rowA] = a1.w;
        Bs[colA + 0][rowA] = w0.x; Bs[colA + 1][rowA] = w0.y;
        Bs[colA + 2][rowA] = w0.z; Bs[colA + 3][rowA] = w0.w;
        Bs[colA + 4][rowA] = w1.x; Bs[colA + 5][rowA] = w1.y;
        Bs[colA + 6][rowA] = w1.z; Bs[colA + 7][rowA] = w1.w;
        __syncthreads();

#pragma unroll
        for (int kk = 0; kk < 16; kk++) {
            float4 av0 = *(const float4*)&As[kk][ty * 8];
            float4 av1 = *(const float4*)&As[kk][ty * 8 + 4];
            ulonglong2 bv0 = *(const ulonglong2*)&Bs[kk][tx * 8];
            ulonglong2 bv1 = *(const ulonglong2*)&Bs[kk][tx * 8 + 4];
            unsigned long long br[4] = {bv0.x, bv0.y, bv1.x, bv1.y};
            float ar[8] = {av0.x, av0.y, av0.z, av0.w,
                           av1.x, av1.y, av1.z, av1.w};
#pragma unroll
            for (int i = 0; i < 8; i++) {
                unsigned long long aa = pack2(ar[i], ar[i]);
#pragma unroll
                for (int jp = 0; jp < 4; jp++) fma2(acc[i][jp], aa, br[jp]);
            }
        }
    }

#pragma unroll
    for (int i = 0; i < 8; i++) {
        int m = mt * 128 + ty * 8 + i;
        if (m < KSEL) {
            float* orow = out + ((size_t)b * KSEL + m) * O_ + o0 + tx * 8;
#pragma unroll
            for (int jp = 0; jp < 4; jp++) {
                float c0, c1;
                unpack2(acc[i][jp], c0, c1);
                int o = o0 + tx * 8 + jp * 2;
                float2 v = make_float2(c0 + bp[o], c1 + bp[o + 1]);
                *(float2*)&orow[jp * 2] = v;
            }
        }
    }
}

// =====================================================================
// Entry point
// =====================================================================
extern "C" void kernel_launch(void* const* d_in, const int* in_sizes, int n_in,
                              void* d_out, int out_size) {
    (void)in_sizes; (void)n_in; (void)out_size;
    const float* x  = (const float*)d_in[0];
    const float* W1 = (const float*)d_in[1];
    const float* b1 = (const float*)d_in[2];
    const float* W2 = (const float*)d_in[3];
    // d_in[4] = b2: constant shift on scores, irrelevant to topk -> unused
    const float* Wp = (const float*)d_in[5];
    const float* bp = (const float*)d_in[6];
    float* out = (float*)d_out;

    score_kernel<<<TOK / 128, 256>>>(x, W1, b1, W2);
    topk_kernel<<<B_, 256>>>();
    proj_kernel<<<dim3(O_ / 128, (KSEL + 127) / 128, B_), 256>>>(x, Wp, bp, out);
}

// round 4
// speedup vs baseline: 2.3730x; 2.3703x over previous
#include <cuda_runtime.h>
#include <cuda_fp16.h>
#include <cfloat>
#include <cstdint>

#define B_   16
#define N_   4096
#define D_   1024
#define H_   512
#define O_   4096
#define KSEL 200
#define TOK  (B_ * N_)        // 65536
#define CMAX 320
#define CTILES 10             // CMAX/32

// Scratch globals (no cudaMalloc allowed)
__device__ float g_part[4 * TOK];          // approx score partials per h-quarter
__device__ int   g_cand[B_ * CMAX];
__device__ int   g_ccount[B_];
__device__ float g_cpart[4 * B_ * CMAX];   // exact score partials per h-quarter
__device__ int   g_topk[B_ * KSEL];

// ---------------- helpers ----------------
__device__ __forceinline__ uint32_t smem_u32(const void* p) {
    uint32_t a;
    asm("{ .reg .u64 t; cvta.to.shared.u64 t, %1; cvt.u32.u64 %0, t; }" : "=r"(a) : "l"(p));
    return a;
}
__device__ __forceinline__ float gelu_exact(float v) {
    return 0.5f * v * (1.0f + erff(v * 0.70710678118654752440f));
}
__device__ __forceinline__ void ldsm4(uint32_t* r, uint32_t addr) {
    asm volatile("ldmatrix.sync.aligned.m8n8.x4.shared.b16 {%0,%1,%2,%3}, [%4];"
                 : "=r"(r[0]), "=r"(r[1]), "=r"(r[2]), "=r"(r[3]) : "r"(addr));
}
__device__ __forceinline__ void mma16816(float* c, const uint32_t* a, const uint32_t* b) {
    asm volatile("mma.sync.aligned.m16n8k16.row.col.f32.f16.f16.f32 "
                 "{%0,%1,%2,%3}, {%4,%5,%6,%7}, {%8,%9}, {%0,%1,%2,%3};"
                 : "+f"(c[0]), "+f"(c[1]), "+f"(c[2]), "+f"(c[3])
                 : "r"(a[0]), "r"(a[1]), "r"(a[2]), "r"(a[3]), "r"(b[0]), "r"(b[1]));
}

#define TSTRIDE 80            // 64B data + 16B pad per 128-row tile row (conflict-free ldmatrix)
#define TILESZ  (128 * TSTRIDE)   // 10240 bytes

// =====================================================================
// Kernel 1: approx scores via 1x fp16 HMMA, fused GELU.W2 partial reduce
// grid (4 hq, 512 m-tiles), 256 thr (8 warps: wm in {0,1} x wn in 0..3)
// =====================================================================
__global__ void __launch_bounds__(256)
approx_score_kernel(const float* __restrict__ x, const float* __restrict__ W1,
                    const float* __restrict__ b1, const float* __restrict__ W2) {
    __shared__ __align__(16) unsigned char tiles[2][2][TILESZ];   // [buf][A/B]
    __shared__ float red[128][4];

    const int t = threadIdx.x, lane = t & 31, w = t >> 5;
    const int hq = blockIdx.x, m0 = blockIdx.y * 128;
    const int wm = w & 1, wn = w >> 1;
    const int lrow = t >> 1;
    const float* Ag = x  + (size_t)(m0 + lrow) * D_ + (t & 1) * 16;
    const float* Bg = W1 + (size_t)(hq * 128 + lrow) * D_ + (t & 1) * 16;
    const uint32_t smb   = smem_u32(&tiles[0][0][0]);
    const uint32_t stoff = (uint32_t)lrow * TSTRIDE + (t & 1) * 32;

    float4 av[4], bv[4];
#pragma unroll
    for (int q = 0; q < 4; q++) { av[q] = *(const float4*)(Ag + 4 * q); bv[q] = *(const float4*)(Bg + 4 * q); }
#pragma unroll
    for (int q = 0; q < 4; q++) {
        __half2 h0 = __floats2half2_rn(av[q].x, av[q].y), h1 = __floats2half2_rn(av[q].z, av[q].w);
        *(uint32_t*)&tiles[0][0][stoff + 8 * q]     = *(uint32_t*)&h0;
        *(uint32_t*)&tiles[0][0][stoff + 8 * q + 4] = *(uint32_t*)&h1;
        __half2 g0 = __floats2half2_rn(bv[q].x, bv[q].y), g1 = __floats2half2_rn(bv[q].z, bv[q].w);
        *(uint32_t*)&tiles[0][1][stoff + 8 * q]     = *(uint32_t*)&g0;
        *(uint32_t*)&tiles[0][1][stoff + 8 * q + 4] = *(uint32_t*)&g1;
    }
    __syncthreads();

    float c[4][4][4];
#pragma unroll
    for (int mi = 0; mi < 4; mi++)
#pragma unroll
        for (int nj = 0; nj < 4; nj++)
#pragma unroll
            for (int e = 0; e < 4; e++) c[mi][nj][e] = 0.0f;

    for (int j = 0; j < 32; j++) {
        const int buf = j & 1;
        if (j < 31) {
            const int k0 = (j + 1) * 32;
#pragma unroll
            for (int q = 0; q < 4; q++) { av[q] = *(const float4*)(Ag + k0 + 4 * q); bv[q] = *(const float4*)(Bg + k0 + 4 * q); }
        }
        const uint32_t Abase = smb + (uint32_t)buf * 2 * TILESZ;
        const uint32_t Bbase = Abase + TILESZ;
#pragma unroll
        for (int ks = 0; ks < 2; ks++) {
            const int k0h = ks * 16;
            uint32_t Af[4][4], Bf[2][4];
#pragma unroll
            for (int mi = 0; mi < 4; mi++)
                ldsm4(Af[mi], Abase + (uint32_t)(64 * wm + 16 * mi + (lane & 7) + 8 * ((lane >> 3) & 1)) * TSTRIDE
                              + (uint32_t)(k0h + 8 * (lane >> 4)) * 2);
#pragma unroll
            for (int np = 0; np < 2; np++)
                ldsm4(Bf[np], Bbase + (uint32_t)(32 * wn + 16 * np + (lane & 7) + 8 * (lane >> 4)) * TSTRIDE
                              + (uint32_t)(k0h + 8 * ((lane >> 3) & 1)) * 2);
#pragma unroll
            for (int mi = 0; mi < 4; mi++)
#pragma unroll
                for (int nj = 0; nj < 4; nj++)
                    mma16816(c[mi][nj], Af[mi], &Bf[nj >> 1][(nj & 1) * 2]);
        }
        if (j < 31) {
            const int ob = (j + 1) & 1;
#pragma unroll
            for (int q = 0; q < 4; q++) {
                __half2 h0 = __floats2half2_rn(av[q].x, av[q].y), h1 = __floats2half2_rn(av[q].z, av[q].w);
                *(uint32_t*)&tiles[ob][0][stoff + 8 * q]     = *(uint32_t*)&h0;
                *(uint32_t*)&tiles[ob][0][stoff + 8 * q + 4] = *(uint32_t*)&h1;
                __half2 g0 = __floats2half2_rn(bv[q].x, bv[q].y), g1 = __floats2half2_rn(bv[q].z, bv[q].w);
                *(uint32_t*)&tiles[ob][1][stoff + 8 * q]     = *(uint32_t*)&g0;
                *(uint32_t*)&tiles[ob][1][stoff + 8 * q + 4] = *(uint32_t*)&g1;
            }
        }
        __syncthreads();
    }

    // epilogue: +b1, GELU, .W2 -> per-row partial
    float pr[4][2];
#pragma unroll
    for (int mi = 0; mi < 4; mi++) { pr[mi][0] = 0.0f; pr[mi][1] = 0.0f; }
#pragma unroll
    for (int mi = 0; mi < 4; mi++)
#pragma unroll
        for (int nj = 0; nj < 4; nj++)
#pragma unroll
            for (int e = 0; e < 4; e++) {
                const int h = hq * 128 + 32 * wn + 8 * nj + 2 * (lane & 3) + (e & 1);
                const float v = c[mi][nj][e] + __ldg(&b1[h]);
                pr[mi][e >> 1] += gelu_exact(v) * __ldg(&W2[h]);
            }
#pragma unroll
    for (int mi = 0; mi < 4; mi++)
#pragma unroll
        for (int rh = 0; rh < 2; rh++) {
            float p = pr[mi][rh];
            p += __shfl_xor_sync(0xffffffffu, p, 1);
            p += __shfl_xor_sync(0xffffffffu, p, 2);
            if ((lane & 3) == 0) {
                const int row = 64 * wm + 16 * mi + (lane >> 2) + 8 * rh;
                red[row][wn] = p;
            }
        }
    __syncthreads();
    if (t < 128)
        g_part[hq * TOK + m0 + t] = red[t][0] + red[t][1] + red[t][2] + red[t][3];
}

// =====================================================================
// Kernel 2: per-batch radix-select threshold at rank 256, compact candidates
// =====================================================================
__global__ void __launch_bounds__(256)
radix_cand_kernel() {
    __shared__ uint32_t key[N_];
    __shared__ int hist[256];
    __shared__ uint32_t s_prefix;
    __shared__ int s_remaining, s_cnt;
    const int b = blockIdx.x, t = threadIdx.x;

    for (int i = t; i < N_; i += 256) {
        const int g = b * N_ + i;
        const float s = g_part[g] + g_part[TOK + g] + g_part[2 * TOK + g] + g_part[3 * TOK + g];
        const uint32_t u = __float_as_uint(s);
        key[i] = (u & 0x80000000u) ? ~u : (u | 0x80000000u);
    }
    if (t == 0) { s_prefix = 0; s_remaining = 256; s_cnt = 0; }
    __syncthreads();

    for (int pass = 0; pass < 3; pass++) {
        const int shift = 24 - pass * 8;
        hist[t & 255] = 0;
        __syncthreads();
        const uint32_t pref = s_prefix;
        for (int i = t; i < N_; i += 256) {
            const uint32_t k = key[i];
            const bool match = (pass == 0) || ((k >> (shift + 8)) == pref);
            if (match) atomicAdd(&hist[(k >> shift) & 255], 1);
        }
        __syncthreads();
        if (t == 0) {
            int rem = s_remaining, acc = 0, v = 255;
            for (; v > 0; v--) { if (acc + hist[v] >= rem) break; acc += hist[v]; }
            s_prefix = (pref << 8) | (uint32_t)v;
            s_remaining = rem - acc;
        }
        __syncthreads();
    }

    const uint32_t thr = s_prefix;    // 24-bit prefix threshold
    for (int i = t; i < N_; i += 256) {
        if ((key[i] >> 8) >= thr) {
            const int pos = atomicAdd(&s_cnt, 1);
            if (pos < CMAX) g_cand[b * CMAX + pos] = i;
        }
    }
    __syncthreads();
    const int cnt = min(s_cnt, CMAX);
    if (t == 0) g_ccount[b] = cnt;
    for (int i = cnt + t; i < CMAX; i += 256) g_cand[b * CMAX + i] = 0;
}

// =====================================================================
// Kernel 3: exact fp32 rescoring of candidates (32 cand x 128 h per block)
// grid (CTILES, 4, B_)
// =====================================================================
__global__ void __launch_bounds__(256)
exact_score_kernel(const float* __restrict__ x, const float* __restrict__ W1,
                   const float* __restrict__ b1, const float* __restrict__ W2) {
    const int ct = blockIdx.x, hq = blockIdx.y, b = blockIdx.z;
    if (ct * 32 >= g_ccount[b]) return;

    __shared__ float As[32][33];
    __shared__ float Bs[32][128];
    __shared__ int cidx[32];
    __shared__ float epr[32][17];
    const int t = threadIdx.x;
    if (t < 32) cidx[t] = g_cand[b * CMAX + ct * 32 + t];
    __syncthreads();

    const int tm = t >> 4, tn = t & 15;
    float acc0[8], acc1[8];
#pragma unroll
    for (int j = 0; j < 8; j++) { acc0[j] = 0.0f; acc1[j] = 0.0f; }

    const int ar = t >> 3, akq = (t & 7) * 4;
    const int br = t >> 1, bk16 = (t & 1) * 16;
    const float* Agr = x  + ((size_t)b * N_ + cidx[ar]) * D_ + akq;
    const float* Bgr = W1 + (size_t)(hq * 128 + br) * D_ + bk16;

    for (int k0 = 0; k0 < D_; k0 += 32) {
        const float4 a = *(const float4*)(Agr + k0);
        float4 bw[4];
#pragma unroll
        for (int q = 0; q < 4; q++) bw[q] = *(const float4*)(Bgr + k0 + 4 * q);
        __syncthreads();
        As[ar][akq + 0] = a.x; As[ar][akq + 1] = a.y; As[ar][akq + 2] = a.z; As[ar][akq + 3] = a.w;
#pragma unroll
        for (int q = 0; q < 4; q++) {
            Bs[bk16 + 4 * q + 0][br] = bw[q].x;
            Bs[bk16 + 4 * q + 1][br] = bw[q].y;
            Bs[bk16 + 4 * q + 2][br] = bw[q].z;
            Bs[bk16 + 4 * q + 3][br] = bw[q].w;
        }
        __syncthreads();
#pragma unroll
        for (int kk = 0; kk < 32; kk++) {
            const float a0 = As[2 * tm][kk], a1 = As[2 * tm + 1][kk];
            const float4 q0 = *(const float4*)&Bs[kk][tn * 8];
            const float4 q1 = *(const float4*)&Bs[kk][tn * 8 + 4];
            acc0[0] += a0 * q0.x; acc0[1] += a0 * q0.y; acc0[2] += a0 * q0.z; acc0[3] += a0 * q0.w;
            acc0[4] += a0 * q1.x; acc0[5] += a0 * q1.y; acc0[6] += a0 * q1.z; acc0[7] += a0 * q1.w;
            acc1[0] += a1 * q0.x; acc1[1] += a1 * q0.y; acc1[2] += a1 * q0.z; acc1[3] += a1 * q0.w;
            acc1[4] += a1 * q1.x; acc1[5] += a1 * q1.y; acc1[6] += a1 * q1.z; acc1[7] += a1 * q1.w;
        }
    }

    float p0 = 0.0f, p1 = 0.0f;
#pragma unroll
    for (int j = 0; j < 8; j++) {
        const int h = hq * 128 + tn * 8 + j;
        const float bb = __ldg(&b1[h]), ww = __ldg(&W2[h]);
        p0 += gelu_exact(acc0[j] + bb) * ww;
        p1 += gelu_exact(acc1[j] + bb) * ww;
    }
    epr[2 * tm][tn] = p0; epr[2 * tm + 1][tn] = p1;
    __syncthreads();
    if (t < 32) {
        float s = 0.0f;
#pragma unroll
        for (int j = 0; j < 16; j++) s += epr[t][j];
        g_cpart[((hq * B_) + b) * CMAX + ct * 32 + t] = s;
    }
}

// =====================================================================
// Kernel 4: final exact top-200 ordering among candidates
// =====================================================================
__global__ void __launch_bounds__(256)
final_topk_kernel() {
    __shared__ float cs[CMAX];
    __shared__ int   cid[CMAX];
    __shared__ int   cslot[CMAX];  // identity, kept via parallel arrays
    __shared__ float wv[8]; __shared__ int wi[8]; __shared__ int ws[8];
    const int b = blockIdx.x, t = threadIdx.x;
    const int cnt = g_ccount[b];

    for (int i = t; i < CMAX; i += 256) {
        if (i < cnt) {
            float s = 0.0f;
#pragma unroll
            for (int hq = 0; hq < 4; hq++) s += g_cpart[((hq * B_) + b) * CMAX + i];
            cs[i] = s; cid[i] = g_cand[b * CMAX + i];
        } else { cs[i] = -FLT_MAX; cid[i] = 0x7fffffff; }
        cslot[i] = i;
    }
    __syncthreads();

    for (int it = 0; it < KSEL; it++) {
        float bv = -FLT_MAX; int bi = 0x7fffffff, bs = 0;
        for (int i = t; i < CMAX; i += 256) {
            const float v = cs[i]; const int id = cid[i];
            if (v > bv || (v == bv && id < bi)) { bv = v; bi = id; bs = i; }
        }
#pragma unroll
        for (int off = 16; off > 0; off >>= 1) {
            const float ov = __shfl_down_sync(0xffffffffu, bv, off);
            const int   oi = __shfl_down_sync(0xffffffffu, bi, off);
            const int   os = __shfl_down_sync(0xffffffffu, bs, off);
            if (ov > bv || (ov == bv && oi < bi)) { bv = ov; bi = oi; bs = os; }
        }
        if ((t & 31) == 0) { wv[t >> 5] = bv; wi[t >> 5] = bi; ws[t >> 5] = bs; }
        __syncthreads();
        if (t == 0) {
            for (int q = 1; q < 8; q++)
                if (wv[q] > bv || (wv[q] == bv && wi[q] < bi)) { bv = wv[q]; bi = wi[q]; bs = ws[q]; }
            g_topk[b * KSEL + it] = bi;
            cs[bs] = -FLT_MAX;
        }
        __syncthreads();
    }
}

// =====================================================================
// Kernel 5: projection via 3-product fp16 split HMMA
// grid (32 o-tiles, 25 packed row-tiles), 256 thr
// =====================================================================
__global__ void __launch_bounds__(256)
proj_kernel(const float* __restrict__ x, const float* __restrict__ Wp,
            const float* __restrict__ bp, float* __restrict__ out) {
    extern __shared__ __align__(16) unsigned char dsm[];   // [2][4][TILESZ] : Ahi,Alo,Bhi,Blo
    __shared__ int stok[128], sbat[128];

    const int t = threadIdx.x, lane = t & 31, w = t >> 5;
    const int wm = w & 1, wn = w >> 1;
    const int o0 = blockIdx.x * 128, r0 = blockIdx.y * 128;
    if (t < 128) { const int R = r0 + t; stok[t] = g_topk[R]; sbat[t] = R / KSEL; }
    __syncthreads();

    const int lrow = t >> 1;
    const float* Ag = x  + ((size_t)sbat[lrow] * N_ + stok[lrow]) * D_ + (t & 1) * 16;
    const float* Bg = Wp + (size_t)(o0 + lrow) * D_ + (t & 1) * 16;
    const uint32_t smb   = smem_u32(dsm);
    const uint32_t stoff = (uint32_t)lrow * TSTRIDE + (t & 1) * 32;

    float4 av[4], bv[4];
#pragma unroll
    for (int q = 0; q < 4; q++) { av[q] = *(const float4*)(Ag + 4 * q); bv[q] = *(const float4*)(Bg + 4 * q); }

    auto split_store = [&](int buf) {
        unsigned char* base = dsm + (size_t)buf * 4 * TILESZ;
#pragma unroll
        for (int q = 0; q < 4; q++) {
            float4 v = av[q];
            __half2 h0 = __floats2half2_rn(v.x, v.y), h1 = __floats2half2_rn(v.z, v.w);
            float2 f0 = __half22float2(h0), f1 = __half22float2(h1);
            __half2 l0 = __floats2half2_rn(v.x - f0.x, v.y - f0.y);
            __half2 l1 = __floats2half2_rn(v.z - f1.x, v.w - f1.y);
            *(uint32_t*)(base + stoff + 8 * q)              = *(uint32_t*)&h0;
            *(uint32_t*)(base + stoff + 8 * q + 4)          = *(uint32_t*)&h1;
            *(uint32_t*)(base + TILESZ + stoff + 8 * q)     = *(uint32_t*)&l0;
            *(uint32_t*)(base + TILESZ + stoff + 8 * q + 4) = *(uint32_t*)&l1;
            v = bv[q];
            h0 = __floats2half2_rn(v.x, v.y); h1 = __floats2half2_rn(v.z, v.w);
            f0 = __half22float2(h0); f1 = __half22float2(h1);
            l0 = __floats2half2_rn(v.x - f0.x, v.y - f0.y);
            l1 = __floats2half2_rn(v.z - f1.x, v.w - f1.y);
            *(uint32_t*)(base + 2 * TILESZ + stoff + 8 * q)     = *(uint32_t*)&h0;
            *(uint32_t*)(base + 2 * TILESZ + stoff + 8 * q + 4) = *(uint32_t*)&h1;
            *(uint32_t*)(base + 3 * TILESZ + stoff + 8 * q)     = *(uint32_t*)&l0;
            *(uint32_t*)(base + 3 * TILESZ + stoff + 8 * q + 4) = *(uint32_t*)&l1;
        }
    };
    split_store(0);
    __syncthreads();

    float c[4][4][4];
#pragma unroll
    for (int mi = 0; mi < 4; mi++)
#pragma unroll
        for (int nj = 0; nj < 4; nj++)
#pragma unroll
            for (int e = 0; e < 4; e++) c[mi][nj][e] = 0.0f;

    for (int j = 0; j < 32; j++) {
        const int buf = j & 1;
        if (j < 31) {
            const int k0 = (j + 1) * 32;
#pragma unroll
            for (int q = 0; q < 4; q++) { av[q] = *(const float4*)(Ag + k0 + 4 * q); bv[q] = *(const float4*)(Bg + k0 + 4 * q); }
        }
        const uint32_t Ahi = smb + (uint32_t)buf * 4 * TILESZ;
        const uint32_t Alo = Ahi + TILESZ;
        const uint32_t Bhi = Ahi + 2 * TILESZ;
        const uint32_t Blo = Ahi + 3 * TILESZ;
        const uint32_t aoff = (uint32_t)(64 * wm + (lane & 7) + 8 * ((lane >> 3) & 1)) * TSTRIDE + (uint32_t)(8 * (lane >> 4)) * 2;
        const uint32_t boff = (uint32_t)(32 * wn + (lane & 7) + 8 * (lane >> 4)) * TSTRIDE + (uint32_t)(8 * ((lane >> 3) & 1)) * 2;
#pragma unroll
        for (int ks = 0; ks < 2; ks++) {
            const uint32_t kb = (uint32_t)(ks * 16) * 2;
            uint32_t Ah[4][4], Al[4][4], Bh[2][4], Bl[2][4];
#pragma unroll
            for (int mi = 0; mi < 4; mi++) {
                ldsm4(Ah[mi], Ahi + aoff + (uint32_t)(16 * mi) * TSTRIDE + kb);
                ldsm4(Al[mi], Alo + aoff + (uint32_t)(16 * mi) * TSTRIDE + kb);
            }
#pragma unroll
            for (int np = 0; np < 2; np++) {
                ldsm4(Bh[np], Bhi + boff + (uint32_t)(16 * np) * TSTRIDE + kb);
                ldsm4(Bl[np], Blo + boff + (uint32_t)(16 * np) * TSTRIDE + kb);
            }
#pragma unroll
            for (int mi = 0; mi < 4; mi++)
#pragma unroll
                for (int nj = 0; nj < 4; nj++) {
                    mma16816(c[mi][nj], Ah[mi], &Bh[nj >> 1][(nj & 1) * 2]);
                    mma16816(c[mi][nj], Ah[mi], &Bl[nj >> 1][(nj & 1) * 2]);
                    mma16816(c[mi][nj], Al[mi], &Bh[nj >> 1][(nj & 1) * 2]);
                }
        }
        if (j < 31) split_store((j + 1) & 1);
        __syncthreads();
    }

    // epilogue: +bp, store float2
#pragma unroll
    for (int mi = 0; mi < 4; mi++)
#pragma unroll
        for (int nj = 0; nj < 4; nj++)
#pragma unroll
            for (int rh = 0; rh < 2; rh++) {
                const int R   = r0 + 64 * wm + 16 * mi + (lane >> 2) + 8 * rh;
                const int oc  = o0 + 32 * wn + 8 * nj + 2 * (lane & 3);
                float2 v;
                v.x = c[mi][nj][2 * rh + 0] + __ldg(&bp[oc]);
                v.y = c[mi][nj][2 * rh + 1] + __ldg(&bp[oc + 1]);
                *(float2*)(out + (size_t)R * O_ + oc) = v;
            }
}

// =====================================================================
// Entry point
// =====================================================================
extern "C" void kernel_launch(void* const* d_in, const int* in_sizes, int n_in,
                              void* d_out, int out_size) {
    (void)in_sizes; (void)n_in; (void)out_size;
    const float* x  = (const float*)d_in[0];
    const float* W1 = (const float*)d_in[1];
    const float* b1 = (const float*)d_in[2];
    const float* W2 = (const float*)d_in[3];
    // d_in[4] = b2: constant shift, irrelevant to topk ordering
    const float* Wp = (const float*)d_in[5];
    const float* bp = (const float*)d_in[6];
    float* out = (float*)d_out;

    static int inited = 0;
    if (!inited) {
        cudaFuncSetAttribute(proj_kernel, cudaFuncAttributeMaxDynamicSharedMemorySize, 8 * TILESZ);
        inited = 1;
    }

    approx_score_kernel<<<dim3(4, TOK / 128), 256>>>(x, W1, b1, W2);
    radix_cand_kernel<<<B_, 256>>>();
    exact_score_kernel<<<dim3(CTILES, 4, B_), 256>>>(x, W1, b1, W2);
    final_topk_kernel<<<B_, 256>>>();
    proj_kernel<<<dim3(O_ / 128, (B_ * KSEL) / 128), 256, 8 * TILESZ>>>(x, Wp, bp, out);
}

// round 5
// speedup vs baseline: 2.4270x; 1.0228x over previous
#include <cuda_runtime.h>
#include <cuda_fp16.h>
#include <cfloat>
#include <cstdint>

#define B_   16
#define N_   4096
#define D_   1024
#define H_   512
#define O_   4096
#define KSEL 200
#define TOK  (B_ * N_)        // 65536
#define RTOT (B_ * KSEL)      // 3200 output rows
#define CMAX 320
#define CTILES 10             // CMAX/32

// Scratch globals (no cudaMalloc allowed)
__device__ float  g_part[4 * TOK];          // approx score partials per h-quarter
__device__ int    g_cand[B_ * CMAX];
__device__ int    g_ccount[B_];
__device__ float  g_cpart[4 * B_ * CMAX];   // exact score partials per h-quarter
__device__ int    g_topk[B_ * KSEL];
__device__ __half g_w1h[H_ * D_];           // W1 in fp16 (approx only)
__device__ __half g_wphi[O_ * D_];          // Wp hi/lo split
__device__ __half g_wplo[O_ * D_];
__device__ __half g_xhi[RTOT * D_];         // gathered selected rows hi/lo
__device__ __half g_xlo[RTOT * D_];

// ---------------- helpers ----------------
__device__ __forceinline__ uint32_t smem_u32(const void* p) {
    uint32_t a;
    asm("{ .reg .u64 t; cvta.to.shared.u64 t, %1; cvt.u32.u64 %0, t; }" : "=r"(a) : "l"(p));
    return a;
}
__device__ __forceinline__ float gelu_exact(float v) {
    return 0.5f * v * (1.0f + erff(v * 0.70710678118654752440f));
}
__device__ __forceinline__ void ldsm4(uint32_t* r, uint32_t addr) {
    asm volatile("ldmatrix.sync.aligned.m8n8.x4.shared.b16 {%0,%1,%2,%3}, [%4];"
                 : "=r"(r[0]), "=r"(r[1]), "=r"(r[2]), "=r"(r[3]) : "r"(addr));
}
__device__ __forceinline__ void mma16816(float* c, const uint32_t* a, const uint32_t* b) {
    asm volatile("mma.sync.aligned.m16n8k16.row.col.f32.f16.f16.f32 "
                 "{%0,%1,%2,%3}, {%4,%5,%6,%7}, {%8,%9}, {%0,%1,%2,%3};"
                 : "+f"(c[0]), "+f"(c[1]), "+f"(c[2]), "+f"(c[3])
                 : "r"(a[0]), "r"(a[1]), "r"(a[2]), "r"(a[3]), "r"(b[0]), "r"(b[1]));
}
// f32x2 packed FMA helpers
__device__ __forceinline__ unsigned long long pack2(float lo, float hi) {
    unsigned long long r;
    asm("mov.b64 %0, {%1, %2};" : "=l"(r) : "f"(lo), "f"(hi));
    return r;
}
__device__ __forceinline__ void unpack2(unsigned long long v, float& lo, float& hi) {
    asm("mov.b64 {%0, %1}, %2;" : "=f"(lo), "=f"(hi) : "l"(v));
}
__device__ __forceinline__ void fma2(unsigned long long& c, unsigned long long a,
                                     unsigned long long b) {
    asm("fma.rn.f32x2 %0, %1, %2, %0;" : "+l"(c) : "l"(a), "l"(b));
}

#define TSTRIDE 80                // 64B data + 16B pad (conflict-free ldmatrix)
#define TILESZ  (128 * TSTRIDE)   // 10240 bytes

// =====================================================================
// Convert kernels (run every launch; idempotent, deterministic, ~15us)
// =====================================================================
__global__ void __launch_bounds__(256)
w1_conv_kernel(const float* __restrict__ W1) {
    const int r = blockIdx.x, t = threadIdx.x;
    const float4 v = *(const float4*)(W1 + (size_t)r * D_ + 4 * t);
    const __half2 h0 = __floats2half2_rn(v.x, v.y), h1 = __floats2half2_rn(v.z, v.w);
    *(uint2*)&g_w1h[(size_t)r * D_ + 4 * t] = make_uint2(*(const uint32_t*)&h0, *(const uint32_t*)&h1);
}

__global__ void __launch_bounds__(256)
wp_conv_kernel(const float* __restrict__ Wp) {
    const int r = blockIdx.x, t = threadIdx.x;
    const float4 v = *(const float4*)(Wp + (size_t)r * D_ + 4 * t);
    const __half2 h0 = __floats2half2_rn(v.x, v.y), h1 = __floats2half2_rn(v.z, v.w);
    const float2 f0 = __half22float2(h0), f1 = __half22float2(h1);
    const __half2 l0 = __floats2half2_rn(v.x - f0.x, v.y - f0.y);
    const __half2 l1 = __floats2half2_rn(v.z - f1.x, v.w - f1.y);
    *(uint2*)&g_wphi[(size_t)r * D_ + 4 * t] = make_uint2(*(const uint32_t*)&h0, *(const uint32_t*)&h1);
    *(uint2*)&g_wplo[(size_t)r * D_ + 4 * t] = make_uint2(*(const uint32_t*)&l0, *(const uint32_t*)&l1);
}

__global__ void __launch_bounds__(256)
gather_conv_kernel(const float* __restrict__ x) {
    const int r = blockIdx.x, t = threadIdx.x;
    const int b = r / KSEL;
    const int tok = g_topk[r];
    const float4 v = *(const float4*)(x + ((size_t)b * N_ + tok) * D_ + 4 * t);
    const __half2 h0 = __floats2half2_rn(v.x, v.y), h1 = __floats2half2_rn(v.z, v.w);
    const float2 f0 = __half22float2(h0), f1 = __half22float2(h1);
    const __half2 l0 = __floats2half2_rn(v.x - f0.x, v.y - f0.y);
    const __half2 l1 = __floats2half2_rn(v.z - f1.x, v.w - f1.y);
    *(uint2*)&g_xhi[(size_t)r * D_ + 4 * t] = make_uint2(*(const uint32_t*)&h0, *(const uint32_t*)&h1);
    *(uint2*)&g_xlo[(size_t)r * D_ + 4 * t] = make_uint2(*(const uint32_t*)&l0, *(const uint32_t*)&l1);
}

// =====================================================================
// Kernel 1: approx scores via fp16 HMMA, fused GELU.W2 partial reduce
// grid (4 hq, 512 m-tiles), 256 thr
// =====================================================================
__global__ void __launch_bounds__(256)
approx_score_kernel(const float* __restrict__ x,
                    const float* __restrict__ b1, const float* __restrict__ W2) {
    __shared__ __align__(16) unsigned char tiles[2][2][TILESZ];   // [buf][A/B]
    __shared__ float red[128][4];

    const int t = threadIdx.x, lane = t & 31, w = t >> 5;
    const int hq = blockIdx.x, m0 = blockIdx.y * 128;
    const int wm = w & 1, wn = w >> 1;
    const int lrow = t >> 1;
    const float*  Ag  = x + (size_t)(m0 + lrow) * D_ + (t & 1) * 16;
    const __half* Bgh = g_w1h + (size_t)(hq * 128 + lrow) * D_ + (t & 1) * 16;
    const uint32_t smb   = smem_u32(&tiles[0][0][0]);
    const uint32_t stoff = (uint32_t)lrow * TSTRIDE + (t & 1) * 32;

    float4 av[4];
    uint4 bh[2];
#pragma unroll
    for (int q = 0; q < 4; q++) av[q] = *(const float4*)(Ag + 4 * q);
    bh[0] = *(const uint4*)(Bgh); bh[1] = *(const uint4*)(Bgh + 8);
#pragma unroll
    for (int q = 0; q < 4; q++) {
        const __half2 h0 = __floats2half2_rn(av[q].x, av[q].y), h1 = __floats2half2_rn(av[q].z, av[q].w);
        *(uint32_t*)&tiles[0][0][stoff + 8 * q]     = *(const uint32_t*)&h0;
        *(uint32_t*)&tiles[0][0][stoff + 8 * q + 4] = *(const uint32_t*)&h1;
    }
    *(uint4*)&tiles[0][1][stoff]      = bh[0];
    *(uint4*)&tiles[0][1][stoff + 16] = bh[1];
    __syncthreads();

    float c[4][4][4];
#pragma unroll
    for (int mi = 0; mi < 4; mi++)
#pragma unroll
        for (int nj = 0; nj < 4; nj++)
#pragma unroll
            for (int e = 0; e < 4; e++) c[mi][nj][e] = 0.0f;

    for (int j = 0; j < 32; j++) {
        const int buf = j & 1;
        if (j < 31) {
            const int k0 = (j + 1) * 32;
#pragma unroll
            for (int q = 0; q < 4; q++) av[q] = *(const float4*)(Ag + k0 + 4 * q);
            bh[0] = *(const uint4*)(Bgh + k0); bh[1] = *(const uint4*)(Bgh + k0 + 8);
        }
        const uint32_t Abase = smb + (uint32_t)buf * 2 * TILESZ;
        const uint32_t Bbase = Abase + TILESZ;
#pragma unroll
        for (int ks = 0; ks < 2; ks++) {
            const int k0h = ks * 16;
            uint32_t Af[4][4], Bf[2][4];
#pragma unroll
            for (int mi = 0; mi < 4; mi++)
                ldsm4(Af[mi], Abase + (uint32_t)(64 * wm + 16 * mi + (lane & 7) + 8 * ((lane >> 3) & 1)) * TSTRIDE
                              + (uint32_t)(k0h + 8 * (lane >> 4)) * 2);
#pragma unroll
            for (int np = 0; np < 2; np++)
                ldsm4(Bf[np], Bbase + (uint32_t)(32 * wn + 16 * np + (lane & 7) + 8 * (lane >> 4)) * TSTRIDE
                              + (uint32_t)(k0h + 8 * ((lane >> 3) & 1)) * 2);
#pragma unroll
            for (int mi = 0; mi < 4; mi++)
#pragma unroll
                for (int nj = 0; nj < 4; nj++)
                    mma16816(c[mi][nj], Af[mi], &Bf[nj >> 1][(nj & 1) * 2]);
        }
        if (j < 31) {
            const int ob = (j + 1) & 1;
#pragma unroll
            for (int q = 0; q < 4; q++) {
                const __half2 h0 = __floats2half2_rn(av[q].x, av[q].y), h1 = __floats2half2_rn(av[q].z, av[q].w);
                *(uint32_t*)&tiles[ob][0][stoff + 8 * q]     = *(const uint32_t*)&h0;
                *(uint32_t*)&tiles[ob][0][stoff + 8 * q + 4] = *(const uint32_t*)&h1;
            }
            *(uint4*)&tiles[ob][1][stoff]      = bh[0];
            *(uint4*)&tiles[ob][1][stoff + 16] = bh[1];
        }
        __syncthreads();
    }

    float pr[4][2];
#pragma unroll
    for (int mi = 0; mi < 4; mi++) { pr[mi][0] = 0.0f; pr[mi][1] = 0.0f; }
#pragma unroll
    for (int mi = 0; mi < 4; mi++)
#pragma unroll
        for (int nj = 0; nj < 4; nj++)
#pragma unroll
            for (int e = 0; e < 4; e++) {
                const int h = hq * 128 + 32 * wn + 8 * nj + 2 * (lane & 3) + (e & 1);
                const float v = c[mi][nj][e] + __ldg(&b1[h]);
                pr[mi][e >> 1] += gelu_exact(v) * __ldg(&W2[h]);
            }
#pragma unroll
    for (int mi = 0; mi < 4; mi++)
#pragma unroll
        for (int rh = 0; rh < 2; rh++) {
            float p = pr[mi][rh];
            p += __shfl_xor_sync(0xffffffffu, p, 1);
            p += __shfl_xor_sync(0xffffffffu, p, 2);
            if ((lane & 3) == 0) red[64 * wm + 16 * mi + (lane >> 2) + 8 * rh][wn] = p;
        }
    __syncthreads();
    if (t < 128)
        g_part[hq * TOK + m0 + t] = red[t][0] + red[t][1] + red[t][2] + red[t][3];
}

// =====================================================================
// Kernel 2: per-batch radix-select threshold at rank 256, compact candidates
// =====================================================================
__global__ void __launch_bounds__(256)
radix_cand_kernel() {
    __shared__ uint32_t key[N_];
    __shared__ int hist[256];
    __shared__ uint32_t s_prefix;
    __shared__ int s_remaining, s_cnt;
    const int b = blockIdx.x, t = threadIdx.x;

    for (int i = t; i < N_; i += 256) {
        const int g = b * N_ + i;
        const float s = g_part[g] + g_part[TOK + g] + g_part[2 * TOK + g] + g_part[3 * TOK + g];
        const uint32_t u = __float_as_uint(s);
        key[i] = (u & 0x80000000u) ? ~u : (u | 0x80000000u);
    }
    if (t == 0) { s_prefix = 0; s_remaining = 256; s_cnt = 0; }
    __syncthreads();

    for (int pass = 0; pass < 3; pass++) {
        const int shift = 24 - pass * 8;
        hist[t & 255] = 0;
        __syncthreads();
        const uint32_t pref = s_prefix;
        for (int i = t; i < N_; i += 256) {
            const uint32_t k = key[i];
            const bool match = (pass == 0) || ((k >> (shift + 8)) == pref);
            if (match) atomicAdd(&hist[(k >> shift) & 255], 1);
        }
        __syncthreads();
        if (t == 0) {
            int rem = s_remaining, acc = 0, v = 255;
            for (; v > 0; v--) { if (acc + hist[v] >= rem) break; acc += hist[v]; }
            s_prefix = (pref << 8) | (uint32_t)v;
            s_remaining = rem - acc;
        }
        __syncthreads();
    }

    const uint32_t thr = s_prefix;
    for (int i = t; i < N_; i += 256) {
        if ((key[i] >> 8) >= thr) {
            const int pos = atomicAdd(&s_cnt, 1);
            if (pos < CMAX) g_cand[b * CMAX + pos] = i;
        }
    }
    __syncthreads();
    const int cnt = min(s_cnt, CMAX);
    if (t == 0) g_ccount[b] = cnt;
    for (int i = cnt + t; i < CMAX; i += 256) g_cand[b * CMAX + i] = 0;
}

// =====================================================================
// Kernel 3: exact fp32 rescoring of candidates (FFMA2 inner loop)
// grid (CTILES, 4, B_)
// =====================================================================
__global__ void __launch_bounds__(256)
exact_score_kernel(const float* __restrict__ x, const float* __restrict__ W1,
                   const float* __restrict__ b1, const float* __restrict__ W2) {
    const int ct = blockIdx.x, hq = blockIdx.y, b = blockIdx.z;
    if (ct * 32 >= g_ccount[b]) return;

    __shared__ __align__(16) float As[32][33];
    __shared__ __align__(16) float Bs[32][128];
    __shared__ int cidx[32];
    __shared__ float epr[32][17];
    const int t = threadIdx.x;
    if (t < 32) cidx[t] = g_cand[b * CMAX + ct * 32 + t];
    __syncthreads();

    const int tm = t >> 4, tn = t & 15;
    unsigned long long acc0[4], acc1[4];
#pragma unroll
    for (int j = 0; j < 4; j++) { acc0[j] = pack2(0.0f, 0.0f); acc1[j] = pack2(0.0f, 0.0f); }

    const int ar = t >> 3, akq = (t & 7) * 4;
    const int br = t >> 1, bk16 = (t & 1) * 16;
    const float* Agr = x  + ((size_t)b * N_ + cidx[ar]) * D_ + akq;
    const float* Bgr = W1 + (size_t)(hq * 128 + br) * D_ + bk16;

    for (int k0 = 0; k0 < D_; k0 += 32) {
        const float4 a = *(const float4*)(Agr + k0);
        float4 bw[4];
#pragma unroll
        for (int q = 0; q < 4; q++) bw[q] = *(const float4*)(Bgr + k0 + 4 * q);
        __syncthreads();
        As[ar][akq + 0] = a.x; As[ar][akq + 1] = a.y; As[ar][akq + 2] = a.z; As[ar][akq + 3] = a.w;
#pragma unroll
        for (int q = 0; q < 4; q++) {
            Bs[bk16 + 4 * q + 0][br] = bw[q].x;
            Bs[bk16 + 4 * q + 1][br] = bw[q].y;
            Bs[bk16 + 4 * q + 2][br] = bw[q].z;
            Bs[bk16 + 4 * q + 3][br] = bw[q].w;
        }
        __syncthreads();
#pragma unroll
        for (int kk = 0; kk < 32; kk++) {
            const float a0 = As[2 * tm][kk], a1 = As[2 * tm + 1][kk];
            const unsigned long long aa0 = pack2(a0, a0);
            const unsigned long long aa1 = pack2(a1, a1);
            const unsigned long long* brow = (const unsigned long long*)&Bs[kk][tn * 8];
#pragma unroll
            for (int p = 0; p < 4; p++) { fma2(acc0[p], aa0, brow[p]); fma2(acc1[p], aa1, brow[p]); }
        }
    }

    float p0 = 0.0f, p1 = 0.0f;
#pragma unroll
    for (int p = 0; p < 4; p++) {
        float c0, c1, d0, d1;
        unpack2(acc0[p], c0, c1);
        unpack2(acc1[p], d0, d1);
        const int h = hq * 128 + tn * 8 + 2 * p;
        const float bb0 = __ldg(&b1[h]), ww0 = __ldg(&W2[h]);
        const float bb1 = __ldg(&b1[h + 1]), ww1 = __ldg(&W2[h + 1]);
        p0 += gelu_exact(c0 + bb0) * ww0 + gelu_exact(c1 + bb1) * ww1;
        p1 += gelu_exact(d0 + bb0) * ww0 + gelu_exact(d1 + bb1) * ww1;
    }
    epr[2 * tm][tn] = p0; epr[2 * tm + 1][tn] = p1;
    __syncthreads();
    if (t < 32) {
        float s = 0.0f;
#pragma unroll
        for (int j = 0; j < 16; j++) s += epr[t][j];
        g_cpart[((hq * B_) + b) * CMAX + ct * 32 + t] = s;
    }
}

// =====================================================================
// Kernel 4: rank-by-counting final top-200 (fully parallel, deterministic)
// =====================================================================
__global__ void __launch_bounds__(256)
final_topk_kernel() {
    __shared__ float cs[CMAX];
    __shared__ int   cid[CMAX];
    const int b = blockIdx.x, t = threadIdx.x;
    const int cnt = g_ccount[b];

    for (int i = t; i < CMAX; i += 256) {
        if (i < cnt) {
            float s = 0.0f;
#pragma unroll
            for (int hq = 0; hq < 4; hq++) s += g_cpart[((hq * B_) + b) * CMAX + i];
            cs[i] = s; cid[i] = g_cand[b * CMAX + i];
        } else { cs[i] = -FLT_MAX; cid[i] = 0x7fffffff; }
    }
    __syncthreads();

    for (int i = t; i < CMAX; i += 256) {
        const float si = cs[i];
        const int idi = cid[i];
        if (idi == 0x7fffffff) continue;
        int rank = 0;
#pragma unroll 8
        for (int j = 0; j < CMAX; j++) {
            const float sj = cs[j];
            rank += (sj > si) || (sj == si && cid[j] < idi);
        }
        if (rank < KSEL) g_topk[b * KSEL + rank] = idi;
    }
}

// =====================================================================
// Kernel 5: projection from precomputed fp16 hi/lo operands (3-mma split)
// grid (32 o-tiles, 25 row-tiles), 256 thr, 80KB dynamic smem
// =====================================================================
__global__ void __launch_bounds__(256)
proj_kernel(const float* __restrict__ bp, float* __restrict__ out) {
    extern __shared__ __align__(16) unsigned char dsm[];   // [2][4][TILESZ]: Ahi,Alo,Bhi,Blo

    const int t = threadIdx.x, lane = t & 31, w = t >> 5;
    const int wm = w & 1, wn = w >> 1;
    const int o0 = blockIdx.x * 128, r0 = blockIdx.y * 128;
    const int lrow = t >> 1;

    const __half* Ahg = g_xhi  + (size_t)(r0 + lrow) * D_ + (t & 1) * 16;
    const __half* Alg = g_xlo  + (size_t)(r0 + lrow) * D_ + (t & 1) * 16;
    const __half* Bhg = g_wphi + (size_t)(o0 + lrow) * D_ + (t & 1) * 16;
    const __half* Blg = g_wplo + (size_t)(o0 + lrow) * D_ + (t & 1) * 16;
    const uint32_t smb   = smem_u32(dsm);
    const uint32_t stoff = (uint32_t)lrow * TSTRIDE + (t & 1) * 32;

    uint4 ra[2][2], rb[2][2];
    ra[0][0] = *(const uint4*)(Ahg); ra[0][1] = *(const uint4*)(Ahg + 8);
    ra[1][0] = *(const uint4*)(Alg); ra[1][1] = *(const uint4*)(Alg + 8);
    rb[0][0] = *(const uint4*)(Bhg); rb[0][1] = *(const uint4*)(Bhg + 8);
    rb[1][0] = *(const uint4*)(Blg); rb[1][1] = *(const uint4*)(Blg + 8);

    auto store_tiles = [&](int buf) {
        unsigned char* base = dsm + (size_t)buf * 4 * TILESZ;
        *(uint4*)(base + stoff)                   = ra[0][0];
        *(uint4*)(base + stoff + 16)              = ra[0][1];
        *(uint4*)(base + TILESZ + stoff)          = ra[1][0];
        *(uint4*)(base + TILESZ + stoff + 16)     = ra[1][1];
        *(uint4*)(base + 2 * TILESZ + stoff)      = rb[0][0];
        *(uint4*)(base + 2 * TILESZ + stoff + 16) = rb[0][1];
        *(uint4*)(base + 3 * TILESZ + stoff)      = rb[1][0];
        *(uint4*)(base + 3 * TILESZ + stoff + 16) = rb[1][1];
    };
    store_tiles(0);
    __syncthreads();

    float c[4][4][4];
#pragma unroll
    for (int mi = 0; mi < 4; mi++)
#pragma unroll
        for (int nj = 0; nj < 4; nj++)
#pragma unroll
            for (int e = 0; e < 4; e++) c[mi][nj][e] = 0.0f;

    for (int j = 0; j < 32; j++) {
        const int buf = j & 1;
        if (j < 31) {
            const int k0 = (j + 1) * 32;
            ra[0][0] = *(const uint4*)(Ahg + k0); ra[0][1] = *(const uint4*)(Ahg + k0 + 8);
            ra[1][0] = *(const uint4*)(Alg + k0); ra[1][1] = *(const uint4*)(Alg + k0 + 8);
            rb[0][0] = *(const uint4*)(Bhg + k0); rb[0][1] = *(const uint4*)(Bhg + k0 + 8);
            rb[1][0] = *(const uint4*)(Blg + k0); rb[1][1] = *(const uint4*)(Blg + k0 + 8);
        }
        const uint32_t Ahi = smb + (uint32_t)buf * 4 * TILESZ;
        const uint32_t Alo = Ahi + TILESZ;
        const uint32_t Bhi = Ahi + 2 * TILESZ;
        const uint32_t Blo = Ahi + 3 * TILESZ;
        const uint32_t aoff = (uint32_t)(64 * wm + (lane & 7) + 8 * ((lane >> 3) & 1)) * TSTRIDE + (uint32_t)(8 * (lane >> 4)) * 2;
        const uint32_t boff = (uint32_t)(32 * wn + (lane & 7) + 8 * (lane >> 4)) * TSTRIDE + (uint32_t)(8 * ((lane >> 3) & 1)) * 2;
#pragma unroll
        for (int ks = 0; ks < 2; ks++) {
            const uint32_t kb = (uint32_t)(ks * 16) * 2;
            uint32_t Ah[4][4], Al[4][4], Bh[2][4], Bl[2][4];
#pragma unroll
            for (int mi = 0; mi < 4; mi++) {
                ldsm4(Ah[mi], Ahi + aoff + (uint32_t)(16 * mi) * TSTRIDE + kb);
                ldsm4(Al[mi], Alo + aoff + (uint32_t)(16 * mi) * TSTRIDE + kb);
            }
#pragma unroll
            for (int np = 0; np < 2; np++) {
                ldsm4(Bh[np], Bhi + boff + (uint32_t)(16 * np) * TSTRIDE + kb);
                ldsm4(Bl[np], Blo + boff + (uint32_t)(16 * np) * TSTRIDE + kb);
            }
#pragma unroll
            for (int mi = 0; mi < 4; mi++)
#pragma unroll
                for (int nj = 0; nj < 4; nj++) {
                    mma16816(c[mi][nj], Ah[mi], &Bh[nj >> 1][(nj & 1) * 2]);
                    mma16816(c[mi][nj], Ah[mi], &Bl[nj >> 1][(nj & 1) * 2]);
                    mma16816(c[mi][nj], Al[mi], &Bh[nj >> 1][(nj & 1) * 2]);
                }
        }
        if (j < 31) store_tiles((j + 1) & 1);
        __syncthreads();
    }

#pragma unroll
    for (int mi = 0; mi < 4; mi++)
#pragma unroll
        for (int nj = 0; nj < 4; nj++)
#pragma unroll
            for (int rh = 0; rh < 2; rh++) {
                const int R  = r0 + 64 * wm + 16 * mi + (lane >> 2) + 8 * rh;
                const int oc = o0 + 32 * wn + 8 * nj + 2 * (lane & 3);
                float2 v;
                v.x = c[mi][nj][2 * rh + 0] + __ldg(&bp[oc]);
                v.y = c[mi][nj][2 * rh + 1] + __ldg(&bp[oc + 1]);
                *(float2*)(out + (size_t)R * O_ + oc) = v;
            }
}

// =====================================================================
// Entry point
// =====================================================================
extern "C" void kernel_launch(void* const* d_in, const int* in_sizes, int n_in,
                              void* d_out, int out_size) {
    (void)in_sizes; (void)n_in; (void)out_size;
    const float* x  = (const float*)d_in[0];
    const float* W1 = (const float*)d_in[1];
    const float* b1 = (const float*)d_in[2];
    const float* W2 = (const float*)d_in[3];
    // d_in[4] = b2: constant shift, irrelevant to topk ordering
    const float* Wp = (const float*)d_in[5];
    const float* bp = (const float*)d_in[6];
    float* out = (float*)d_out;

    static int inited = 0;
    if (!inited) {
        cudaFuncSetAttribute(proj_kernel, cudaFuncAttributeMaxDynamicSharedMemorySize, 8 * TILESZ);
        inited = 1;
    }

    w1_conv_kernel<<<H_, 256>>>(W1);
    wp_conv_kernel<<<O_, 256>>>(Wp);
    approx_score_kernel<<<dim3(4, TOK / 128), 256>>>(x, b1, W2);
    radix_cand_kernel<<<B_, 256>>>();
    exact_score_kernel<<<dim3(CTILES, 4, B_), 256>>>(x, W1, b1, W2);
    final_topk_kernel<<<B_, 256>>>();
    gather_conv_kernel<<<RTOT, 256>>>(x);
    proj_kernel<<<dim3(O_ / 128, RTOT / 128), 256, 8 * TILESZ>>>(bp, out);
}

// round 6
// speedup vs baseline: 2.5831x; 1.0643x over previous
#include <cuda_runtime.h>
#include <cuda_fp16.h>
#include <cfloat>
#include <cstdint>

#define B_   16
#define N_   4096
#define D_   1024
#define H_   512
#define O_   4096
#define KSEL 200
#define TOK  (B_ * N_)        // 65536
#define RTOT (B_ * KSEL)      // 3200 output rows
#define CMAX 320
#define CTILES 10             // CMAX/32

// Scratch globals (no cudaMalloc allowed)
__device__ float  g_part[4 * TOK];          // approx score partials per h-quarter
__device__ int    g_cand[B_ * CMAX];
__device__ int    g_ccount[B_];
__device__ float  g_cpart[4 * B_ * CMAX];   // exact score partials per h-quarter
__device__ int    g_topk[B_ * KSEL];
__device__ __half g_xh[(size_t)TOK * D_];   // all of x in fp16 (approx stage)
__device__ __half g_w1h[H_ * D_];           // W1 in fp16 (approx stage)
__device__ __half g_wphi[O_ * D_];          // Wp hi/lo split
__device__ __half g_wplo[O_ * D_];
__device__ __half g_xhi[RTOT * D_];         // gathered selected rows hi/lo
__device__ __half g_xlo[RTOT * D_];

// ---------------- helpers ----------------
__device__ __forceinline__ uint32_t smem_u32(const void* p) {
    uint32_t a;
    asm("{ .reg .u64 t; cvta.to.shared.u64 t, %1; cvt.u32.u64 %0, t; }" : "=r"(a) : "l"(p));
    return a;
}
__device__ __forceinline__ float gelu_exact(float v) {
    return 0.5f * v * (1.0f + erff(v * 0.70710678118654752440f));
}
// fast gelu: only used for candidate SELECTION (margin ~0.12 >> err ~0.01)
__device__ __forceinline__ float gelu_fast(float v) {
    return __fdividef(v, 1.0f + __expf(-1.702f * v));
}
__device__ __forceinline__ void ldsm4(uint32_t* r, uint32_t addr) {
    asm volatile("ldmatrix.sync.aligned.m8n8.x4.shared.b16 {%0,%1,%2,%3}, [%4];"
                 : "=r"(r[0]), "=r"(r[1]), "=r"(r[2]), "=r"(r[3]) : "r"(addr));
}
__device__ __forceinline__ void mma16816(float* c, const uint32_t* a, const uint32_t* b) {
    asm volatile("mma.sync.aligned.m16n8k16.row.col.f32.f16.f16.f32 "
                 "{%0,%1,%2,%3}, {%4,%5,%6,%7}, {%8,%9}, {%0,%1,%2,%3};"
                 : "+f"(c[0]), "+f"(c[1]), "+f"(c[2]), "+f"(c[3])
                 : "r"(a[0]), "r"(a[1]), "r"(a[2]), "r"(a[3]), "r"(b[0]), "r"(b[1]));
}
__device__ __forceinline__ void cpa16(uint32_t dst, const void* src) {
    asm volatile("cp.async.cg.shared.global [%0], [%1], 16;" :: "r"(dst), "l"(src));
}
#define CP_COMMIT() asm volatile("cp.async.commit_group;" ::: "memory")
#define CP_WAIT1()  asm volatile("cp.async.wait_group 1;" ::: "memory")
#define CP_WAIT2()  asm volatile("cp.async.wait_group 2;" ::: "memory")
// f32x2 packed FMA helpers
__device__ __forceinline__ unsigned long long pack2(float lo, float hi) {
    unsigned long long r;
    asm("mov.b64 %0, {%1, %2};" : "=l"(r) : "f"(lo), "f"(hi));
    return r;
}
__device__ __forceinline__ void unpack2(unsigned long long v, float& lo, float& hi) {
    asm("mov.b64 {%0, %1}, %2;" : "=f"(lo), "=f"(hi) : "l"(v));
}
__device__ __forceinline__ void fma2(unsigned long long& c, unsigned long long a,
                                     unsigned long long b) {
    asm("fma.rn.f32x2 %0, %1, %2, %0;" : "+l"(c) : "l"(a), "l"(b));
}

#define TSTRIDE 80                // 64B data + 16B pad (conflict-free ldmatrix)
#define TILESZ  (128 * TSTRIDE)   // 10240 bytes
#define APPROX_SMEM (4 * 2 * TILESZ + 2048)   // 4 stages x (A+B) + red
#define PROJ_SMEM   (3 * 4 * TILESZ)          // 3 stages x (Ahi,Alo,Bhi,Blo)

// =====================================================================
// Convert kernels
// =====================================================================
__global__ void __launch_bounds__(256)
xh_conv_kernel(const float* __restrict__ x) {
    const size_t base = (size_t)blockIdx.x * D_ + 4 * threadIdx.x;
    const float4 v = *(const float4*)(x + base);
    const __half2 h0 = __floats2half2_rn(v.x, v.y), h1 = __floats2half2_rn(v.z, v.w);
    *(uint2*)&g_xh[base] = make_uint2(*(const uint32_t*)&h0, *(const uint32_t*)&h1);
}

__global__ void __launch_bounds__(256)
w1_conv_kernel(const float* __restrict__ W1) {
    const size_t base = (size_t)blockIdx.x * D_ + 4 * threadIdx.x;
    const float4 v = *(const float4*)(W1 + base);
    const __half2 h0 = __floats2half2_rn(v.x, v.y), h1 = __floats2half2_rn(v.z, v.w);
    *(uint2*)&g_w1h[base] = make_uint2(*(const uint32_t*)&h0, *(const uint32_t*)&h1);
}

__global__ void __launch_bounds__(256)
wp_conv_kernel(const float* __restrict__ Wp) {
    const size_t base = (size_t)blockIdx.x * D_ + 4 * threadIdx.x;
    const float4 v = *(const float4*)(Wp + base);
    const __half2 h0 = __floats2half2_rn(v.x, v.y), h1 = __floats2half2_rn(v.z, v.w);
    const float2 f0 = __half22float2(h0), f1 = __half22float2(h1);
    const __half2 l0 = __floats2half2_rn(v.x - f0.x, v.y - f0.y);
    const __half2 l1 = __floats2half2_rn(v.z - f1.x, v.w - f1.y);
    *(uint2*)&g_wphi[base] = make_uint2(*(const uint32_t*)&h0, *(const uint32_t*)&h1);
    *(uint2*)&g_wplo[base] = make_uint2(*(const uint32_t*)&l0, *(const uint32_t*)&l1);
}

__global__ void __launch_bounds__(256)
gather_conv_kernel(const float* __restrict__ x) {
    const int r = blockIdx.x, t = threadIdx.x;
    const int b = r / KSEL;
    const int tok = g_topk[r];
    const float4 v = *(const float4*)(x + ((size_t)b * N_ + tok) * D_ + 4 * t);
    const __half2 h0 = __floats2half2_rn(v.x, v.y), h1 = __floats2half2_rn(v.z, v.w);
    const float2 f0 = __half22float2(h0), f1 = __half22float2(h1);
    const __half2 l0 = __floats2half2_rn(v.x - f0.x, v.y - f0.y);
    const __half2 l1 = __floats2half2_rn(v.z - f1.x, v.w - f1.y);
    *(uint2*)&g_xhi[(size_t)r * D_ + 4 * t] = make_uint2(*(const uint32_t*)&h0, *(const uint32_t*)&h1);
    *(uint2*)&g_xlo[(size_t)r * D_ + 4 * t] = make_uint2(*(const uint32_t*)&l0, *(const uint32_t*)&l1);
}

// =====================================================================
// Kernel 1: approx scores via fp16 HMMA, 4-stage cp.async pipeline
// grid (4 hq, 512 m-tiles), 256 thr
// =====================================================================
__global__ void __launch_bounds__(256)
approx_score_kernel(const float* __restrict__ b1, const float* __restrict__ W2) {
    extern __shared__ __align__(16) unsigned char dsm[];
    float* red = (float*)(dsm + 4 * 2 * TILESZ);   // [128][4]

    const int t = threadIdx.x, lane = t & 31, w = t >> 5;
    const int hq = blockIdx.x, m0 = blockIdx.y * 128;
    const int wm = w & 1, wn = w >> 1;
    const int lrow = t >> 1;
    const __half* Asrc = g_xh  + (size_t)(m0 + lrow) * D_ + (t & 1) * 16;
    const __half* Bsrc = g_w1h + (size_t)(hq * 128 + lrow) * D_ + (t & 1) * 16;
    const uint32_t smb   = smem_u32(dsm);
    const uint32_t stoff = (uint32_t)lrow * TSTRIDE + (t & 1) * 32;

    auto issue = [&](int c, int s) {
        const uint32_t d = smb + (uint32_t)s * 2 * TILESZ + stoff;
        cpa16(d,               Asrc + c * 32);
        cpa16(d + 16,          Asrc + c * 32 + 8);
        cpa16(d + TILESZ,      Bsrc + c * 32);
        cpa16(d + TILESZ + 16, Bsrc + c * 32 + 8);
    };
    issue(0, 0); CP_COMMIT();
    issue(1, 1); CP_COMMIT();
    issue(2, 2); CP_COMMIT();

    float c[4][4][4];
#pragma unroll
    for (int mi = 0; mi < 4; mi++)
#pragma unroll
        for (int nj = 0; nj < 4; nj++)
#pragma unroll
            for (int e = 0; e < 4; e++) c[mi][nj][e] = 0.0f;

    for (int j = 0; j < 32; j++) {
        CP_WAIT2();
        __syncthreads();
        const int slot = j & 3;
        const uint32_t Abase = smb + (uint32_t)slot * 2 * TILESZ;
        const uint32_t Bbase = Abase + TILESZ;
#pragma unroll
        for (int ks = 0; ks < 2; ks++) {
            const int k0h = ks * 16;
            uint32_t Af[4][4], Bf[2][4];
#pragma unroll
            for (int mi = 0; mi < 4; mi++)
                ldsm4(Af[mi], Abase + (uint32_t)(64 * wm + 16 * mi + (lane & 7) + 8 * ((lane >> 3) & 1)) * TSTRIDE
                              + (uint32_t)(k0h + 8 * (lane >> 4)) * 2);
#pragma unroll
            for (int np = 0; np < 2; np++)
                ldsm4(Bf[np], Bbase + (uint32_t)(32 * wn + 16 * np + (lane & 7) + 8 * (lane >> 4)) * TSTRIDE
                              + (uint32_t)(k0h + 8 * ((lane >> 3) & 1)) * 2);
#pragma unroll
            for (int mi = 0; mi < 4; mi++)
#pragma unroll
                for (int nj = 0; nj < 4; nj++)
                    mma16816(c[mi][nj], Af[mi], &Bf[nj >> 1][(nj & 1) * 2]);
        }
        if (j + 3 < 32) issue(j + 3, (j + 3) & 3);
        CP_COMMIT();
    }

    // epilogue: +b1, fast-gelu, .W2 -> per-row partial
    float pr[4][2];
#pragma unroll
    for (int mi = 0; mi < 4; mi++) { pr[mi][0] = 0.0f; pr[mi][1] = 0.0f; }
#pragma unroll
    for (int mi = 0; mi < 4; mi++)
#pragma unroll
        for (int nj = 0; nj < 4; nj++)
#pragma unroll
            for (int e = 0; e < 4; e++) {
                const int h = hq * 128 + 32 * wn + 8 * nj + 2 * (lane & 3) + (e & 1);
                const float v = c[mi][nj][e] + __ldg(&b1[h]);
                pr[mi][e >> 1] += gelu_fast(v) * __ldg(&W2[h]);
            }
    __syncthreads();   // mainloop smem done before red reuse region is safe anyway; keep order
#pragma unroll
    for (int mi = 0; mi < 4; mi++)
#pragma unroll
        for (int rh = 0; rh < 2; rh++) {
            float p = pr[mi][rh];
            p += __shfl_xor_sync(0xffffffffu, p, 1);
            p += __shfl_xor_sync(0xffffffffu, p, 2);
            if ((lane & 3) == 0) red[(64 * wm + 16 * mi + (lane >> 2) + 8 * rh) * 4 + wn] = p;
        }
    __syncthreads();
    if (t < 128)
        g_part[hq * TOK + m0 + t] = red[t * 4 + 0] + red[t * 4 + 1] + red[t * 4 + 2] + red[t * 4 + 3];
}

// =====================================================================
// Kernel 2: per-batch radix-select threshold at rank 256, compact candidates
// =====================================================================
__global__ void __launch_bounds__(256)
radix_cand_kernel() {
    __shared__ uint32_t key[N_];
    __shared__ int hist[256];
    __shared__ uint32_t s_prefix;
    __shared__ int s_remaining, s_cnt;
    const int b = blockIdx.x, t = threadIdx.x;

    for (int i = t; i < N_; i += 256) {
        const int g = b * N_ + i;
        const float s = g_part[g] + g_part[TOK + g] + g_part[2 * TOK + g] + g_part[3 * TOK + g];
        const uint32_t u = __float_as_uint(s);
        key[i] = (u & 0x80000000u) ? ~u : (u | 0x80000000u);
    }
    if (t == 0) { s_prefix = 0; s_remaining = 256; s_cnt = 0; }
    __syncthreads();

    for (int pass = 0; pass < 3; pass++) {
        const int shift = 24 - pass * 8;
        hist[t & 255] = 0;
        __syncthreads();
        const uint32_t pref = s_prefix;
        for (int i = t; i < N_; i += 256) {
            const uint32_t k = key[i];
            const bool match = (pass == 0) || ((k >> (shift + 8)) == pref);
            if (match) atomicAdd(&hist[(k >> shift) & 255], 1);
        }
        __syncthreads();
        if (t == 0) {
            int rem = s_remaining, acc = 0, v = 255;
            for (; v > 0; v--) { if (acc + hist[v] >= rem) break; acc += hist[v]; }
            s_prefix = (pref << 8) | (uint32_t)v;
            s_remaining = rem - acc;
        }
        __syncthreads();
    }

    const uint32_t thr = s_prefix;
    for (int i = t; i < N_; i += 256) {
        if ((key[i] >> 8) >= thr) {
            const int pos = atomicAdd(&s_cnt, 1);
            if (pos < CMAX) g_cand[b * CMAX + pos] = i;
        }
    }
    __syncthreads();
    const int cnt = min(s_cnt, CMAX);
    if (t == 0) g_ccount[b] = cnt;
    for (int i = cnt + t; i < CMAX; i += 256) g_cand[b * CMAX + i] = 0;
}

// =====================================================================
// Kernel 3: exact fp32 rescoring of candidates (FFMA2 inner loop)
// grid (CTILES, 4, B_)
// =====================================================================
__global__ void __launch_bounds__(256)
exact_score_kernel(const float* __restrict__ x, const float* __restrict__ W1,
                   const float* __restrict__ b1, const float* __restrict__ W2) {
    const int ct = blockIdx.x, hq = blockIdx.y, b = blockIdx.z;
    if (ct * 32 >= g_ccount[b]) return;

    __shared__ __align__(16) float As[32][33];
    __shared__ __align__(16) float Bs[32][128];
    __shared__ int cidx[32];
    __shared__ float epr[32][17];
    const int t = threadIdx.x;
    if (t < 32) cidx[t] = g_cand[b * CMAX + ct * 32 + t];
    __syncthreads();

    const int tm = t >> 4, tn = t & 15;
    unsigned long long acc0[4], acc1[4];
#pragma unroll
    for (int j = 0; j < 4; j++) { acc0[j] = pack2(0.0f, 0.0f); acc1[j] = pack2(0.0f, 0.0f); }

    const int ar = t >> 3, akq = (t & 7) * 4;
    const int br = t >> 1, bk16 = (t & 1) * 16;
    const float* Agr = x  + ((size_t)b * N_ + cidx[ar]) * D_ + akq;
    const float* Bgr = W1 + (size_t)(hq * 128 + br) * D_ + bk16;

    for (int k0 = 0; k0 < D_; k0 += 32) {
        const float4 a = *(const float4*)(Agr + k0);
        float4 bw[4];
#pragma unroll
        for (int q = 0; q < 4; q++) bw[q] = *(const float4*)(Bgr + k0 + 4 * q);
        __syncthreads();
        As[ar][akq + 0] = a.x; As[ar][akq + 1] = a.y; As[ar][akq + 2] = a.z; As[ar][akq + 3] = a.w;
#pragma unroll
        for (int q = 0; q < 4; q++) {
            Bs[bk16 + 4 * q + 0][br] = bw[q].x;
            Bs[bk16 + 4 * q + 1][br] = bw[q].y;
            Bs[bk16 + 4 * q + 2][br] = bw[q].z;
            Bs[bk16 + 4 * q + 3][br] = bw[q].w;
        }
        __syncthreads();
#pragma unroll
        for (int kk = 0; kk < 32; kk++) {
            const float a0 = As[2 * tm][kk], a1 = As[2 * tm + 1][kk];
            const unsigned long long aa0 = pack2(a0, a0);
            const unsigned long long aa1 = pack2(a1, a1);
            const unsigned long long* brow = (const unsigned long long*)&Bs[kk][tn * 8];
#pragma unroll
            for (int p = 0; p < 4; p++) { fma2(acc0[p], aa0, brow[p]); fma2(acc1[p], aa1, brow[p]); }
        }
    }

    float p0 = 0.0f, p1 = 0.0f;
#pragma unroll
    for (int p = 0; p < 4; p++) {
        float c0, c1, d0, d1;
        unpack2(acc0[p], c0, c1);
        unpack2(acc1[p], d0, d1);
        const int h = hq * 128 + tn * 8 + 2 * p;
        const float bb0 = __ldg(&b1[h]), ww0 = __ldg(&W2[h]);
        const float bb1 = __ldg(&b1[h + 1]), ww1 = __ldg(&W2[h + 1]);
        p0 += gelu_exact(c0 + bb0) * ww0 + gelu_exact(c1 + bb1) * ww1;
        p1 += gelu_exact(d0 + bb0) * ww0 + gelu_exact(d1 + bb1) * ww1;
    }
    epr[2 * tm][tn] = p0; epr[2 * tm + 1][tn] = p1;
    __syncthreads();
    if (t < 32) {
        float s = 0.0f;
#pragma unroll
        for (int j = 0; j < 16; j++) s += epr[t][j];
        g_cpart[((hq * B_) + b) * CMAX + ct * 32 + t] = s;
    }
}

// =====================================================================
// Kernel 4: rank-by-counting final top-200 (fully parallel, deterministic)
// =====================================================================
__global__ void __launch_bounds__(256)
final_topk_kernel() {
    __shared__ float cs[CMAX];
    __shared__ int   cid[CMAX];
    const int b = blockIdx.x, t = threadIdx.x;
    const int cnt = g_ccount[b];

    for (int i = t; i < CMAX; i += 256) {
        if (i < cnt) {
            float s = 0.0f;
#pragma unroll
            for (int hq = 0; hq < 4; hq++) s += g_cpart[((hq * B_) + b) * CMAX + i];
            cs[i] = s; cid[i] = g_cand[b * CMAX + i];
        } else { cs[i] = -FLT_MAX; cid[i] = 0x7fffffff; }
    }
    __syncthreads();

    for (int i = t; i < CMAX; i += 256) {
        const float si = cs[i];
        const int idi = cid[i];
        if (idi == 0x7fffffff) continue;
        int rank = 0;
#pragma unroll 8
        for (int j = 0; j < CMAX; j++) {
            const float sj = cs[j];
            rank += (sj > si) || (sj == si && cid[j] < idi);
        }
        if (rank < KSEL) g_topk[b * KSEL + rank] = idi;
    }
}

// =====================================================================
// Kernel 5: projection, 3-stage cp.async pipeline, 3-mma fp16 split
// grid (32 o-tiles, 25 row-tiles), 256 thr, 120KB dynamic smem
// =====================================================================
__global__ void __launch_bounds__(256)
proj_kernel(const float* __restrict__ bp, float* __restrict__ out) {
    extern __shared__ __align__(16) unsigned char dsm[];   // [3][4][TILESZ]

    const int t = threadIdx.x, lane = t & 31, w = t >> 5;
    const int wm = w & 1, wn = w >> 1;
    const int o0 = blockIdx.x * 128, r0 = blockIdx.y * 128;
    const int lrow = t >> 1;

    const __half* Ahg = g_xhi  + (size_t)(r0 + lrow) * D_ + (t & 1) * 16;
    const __half* Alg = g_xlo  + (size_t)(r0 + lrow) * D_ + (t & 1) * 16;
    const __half* Bhg = g_wphi + (size_t)(o0 + lrow) * D_ + (t & 1) * 16;
    const __half* Blg = g_wplo + (size_t)(o0 + lrow) * D_ + (t & 1) * 16;
    const uint32_t smb   = smem_u32(dsm);
    const uint32_t stoff = (uint32_t)lrow * TSTRIDE + (t & 1) * 32;

    auto issue = [&](int c, int s) {
        const uint32_t d = smb + (uint32_t)s * 4 * TILESZ + stoff;
        cpa16(d,                   Ahg + c * 32);
        cpa16(d + 16,              Ahg + c * 32 + 8);
        cpa16(d + TILESZ,          Alg + c * 32);
        cpa16(d + TILESZ + 16,     Alg + c * 32 + 8);
        cpa16(d + 2 * TILESZ,      Bhg + c * 32);
        cpa16(d + 2 * TILESZ + 16, Bhg + c * 32 + 8);
        cpa16(d + 3 * TILESZ,      Blg + c * 32);
        cpa16(d + 3 * TILESZ + 16, Blg + c * 32 + 8);
    };
    issue(0, 0); CP_COMMIT();
    issue(1, 1); CP_COMMIT();

    float c[4][4][4];
#pragma unroll
    for (int mi = 0; mi < 4; mi++)
#pragma unroll
        for (int nj = 0; nj < 4; nj++)
#pragma unroll
            for (int e = 0; e < 4; e++) c[mi][nj][e] = 0.0f;

    int slot = 0;
    for (int j = 0; j < 32; j++) {
        CP_WAIT1();
        __syncthreads();
        const uint32_t Ahi = smb + (uint32_t)slot * 4 * TILESZ;
        const uint32_t Alo = Ahi + TILESZ;
        const uint32_t Bhi = Ahi + 2 * TILESZ;
        const uint32_t Blo = Ahi + 3 * TILESZ;
        const uint32_t aoff = (uint32_t)(64 * wm + (lane & 7) + 8 * ((lane >> 3) & 1)) * TSTRIDE + (uint32_t)(8 * (lane >> 4)) * 2;
        const uint32_t boff = (uint32_t)(32 * wn + (lane & 7) + 8 * (lane >> 4)) * TSTRIDE + (uint32_t)(8 * ((lane >> 3) & 1)) * 2;
#pragma unroll
        for (int ks = 0; ks < 2; ks++) {
            const uint32_t kb = (uint32_t)(ks * 16) * 2;
            uint32_t Ah[4][4], Al[4][4], Bh[2][4], Bl[2][4];
#pragma unroll
            for (int mi = 0; mi < 4; mi++) {
                ldsm4(Ah[mi], Ahi + aoff + (uint32_t)(16 * mi) * TSTRIDE + kb);
                ldsm4(Al[mi], Alo + aoff + (uint32_t)(16 * mi) * TSTRIDE + kb);
            }
#pragma unroll
            for (int np = 0; np < 2; np++) {
                ldsm4(Bh[np], Bhi + boff + (uint32_t)(16 * np) * TSTRIDE + kb);
                ldsm4(Bl[np], Blo + boff + (uint32_t)(16 * np) * TSTRIDE + kb);
            }
#pragma unroll
            for (int mi = 0; mi < 4; mi++)
#pragma unroll
                for (int nj = 0; nj < 4; nj++) {
                    mma16816(c[mi][nj], Ah[mi], &Bh[nj >> 1][(nj & 1) * 2]);
                    mma16816(c[mi][nj], Ah[mi], &Bl[nj >> 1][(nj & 1) * 2]);
                    mma16816(c[mi][nj], Al[mi], &Bh[nj >> 1][(nj & 1) * 2]);
                }
        }
        if (j + 2 < 32) issue(j + 2, (j + 2) % 3);
        CP_COMMIT();
        slot = (slot == 2) ? 0 : slot + 1;
    }

#pragma unroll
    for (int mi = 0; mi < 4; mi++)
#pragma unroll
        for (int nj = 0; nj < 4; nj++)
#pragma unroll
            for (int rh = 0; rh < 2; rh++) {
                const int R  = r0 + 64 * wm + 16 * mi + (lane >> 2) + 8 * rh;
                const int oc = o0 + 32 * wn + 8 * nj + 2 * (lane & 3);
                float2 v;
                v.x = c[mi][nj][2 * rh + 0] + __ldg(&bp[oc]);
                v.y = c[mi][nj][2 * rh + 1] + __ldg(&bp[oc + 1]);
                *(float2*)(out + (size_t)R * O_ + oc) = v;
            }
}

// =====================================================================
// Entry point
// =====================================================================
extern "C" void kernel_launch(void* const* d_in, const int* in_sizes, int n_in,
                              void* d_out, int out_size) {
    (void)in_sizes; (void)n_in; (void)out_size;
    const float* x  = (const float*)d_in[0];
    const float* W1 = (const float*)d_in[1];
    const float* b1 = (const float*)d_in[2];
    const float* W2 = (const float*)d_in[3];
    // d_in[4] = b2: constant shift, irrelevant to topk ordering
    const float* Wp = (const float*)d_in[5];
    const float* bp = (const float*)d_in[6];
    float* out = (float*)d_out;

    cudaFuncSetAttribute(approx_score_kernel, cudaFuncAttributeMaxDynamicSharedMemorySize, APPROX_SMEM);
    cudaFuncSetAttribute(proj_kernel,         cudaFuncAttributeMaxDynamicSharedMemorySize, PROJ_SMEM);

    xh_conv_kernel<<<TOK, 256>>>(x);
    w1_conv_kernel<<<H_, 256>>>(W1);
    wp_conv_kernel<<<O_, 256>>>(Wp);
    approx_score_kernel<<<dim3(4, TOK / 128), 256, APPROX_SMEM>>>(b1, W2);
    radix_cand_kernel<<<B_, 256>>>();
    exact_score_kernel<<<dim3(CTILES, 4, B_), 256>>>(x, W1, b1, W2);
    final_topk_kernel<<<B_, 256>>>();
    gather_conv_kernel<<<RTOT, 256>>>(x);
    proj_kernel<<<dim3(O_ / 128, RTOT / 128), 256, PROJ_SMEM>>>(bp, out);
}

// round 7
// speedup vs baseline: 3.2421x; 1.2551x over previous
#include <cuda_runtime.h>
#include <cuda_fp16.h>
#include <cfloat>
#include <cstdint>

#define B_   16
#define N_   4096
#define D_   1024
#define H_   512
#define O_   4096
#define KSEL 200
#define TOK  (B_ * N_)        // 65536
#define RTOT (B_ * KSEL)      // 3200 output rows
#define CMAX 320
#define CT64 5                // CMAX/64 tiles for exact rescore

// Scratch globals (no cudaMalloc allowed)
__device__ float  g_part[4 * TOK];          // approx score partials per h-quarter
__device__ int    g_cand[B_ * CMAX];
__device__ int    g_ccount[B_];
__device__ float  g_cpart[4 * B_ * CMAX];   // exact score partials per h-quarter
__device__ int    g_topk[B_ * KSEL];
__device__ __half g_xh[(size_t)TOK * D_];   // all of x in fp16 (approx stage)
__device__ __half g_w1h[H_ * D_];           // W1 in fp16 (approx stage)
__device__ __half g_wphi[O_ * D_];          // Wp hi/lo split
__device__ __half g_wplo[O_ * D_];
__device__ __half g_xhi[RTOT * D_];         // gathered selected rows hi/lo
__device__ __half g_xlo[RTOT * D_];

// ---------------- helpers ----------------
__device__ __forceinline__ uint32_t smem_u32(const void* p) {
    uint32_t a;
    asm("{ .reg .u64 t; cvta.to.shared.u64 t, %1; cvt.u32.u64 %0, t; }" : "=r"(a) : "l"(p));
    return a;
}
__device__ __forceinline__ float gelu_exact(float v) {
    return 0.5f * v * (1.0f + erff(v * 0.70710678118654752440f));
}
// fast gelu: only used for candidate SELECTION (rank margin 120 >> err)
__device__ __forceinline__ float gelu_fast(float v) {
    return __fdividef(v, 1.0f + __expf(-1.702f * v));
}
__device__ __forceinline__ void ldsm4(uint32_t* r, uint32_t addr) {
    asm volatile("ldmatrix.sync.aligned.m8n8.x4.shared.b16 {%0,%1,%2,%3}, [%4];"
                 : "=r"(r[0]), "=r"(r[1]), "=r"(r[2]), "=r"(r[3]) : "r"(addr));
}
__device__ __forceinline__ void mma16816(float* c, const uint32_t* a, const uint32_t* b) {
    asm volatile("mma.sync.aligned.m16n8k16.row.col.f32.f16.f16.f32 "
                 "{%0,%1,%2,%3}, {%4,%5,%6,%7}, {%8,%9}, {%0,%1,%2,%3};"
                 : "+f"(c[0]), "+f"(c[1]), "+f"(c[2]), "+f"(c[3])
                 : "r"(a[0]), "r"(a[1]), "r"(a[2]), "r"(a[3]), "r"(b[0]), "r"(b[1]));
}
__device__ __forceinline__ void cpa16(uint32_t dst, const void* src) {
    asm volatile("cp.async.cg.shared.global [%0], [%1], 16;" :: "r"(dst), "l"(src));
}
#define CP_COMMIT() asm volatile("cp.async.commit_group;" ::: "memory")
#define CP_WAIT1()  asm volatile("cp.async.wait_group 1;" ::: "memory")
#define CP_WAIT2()  asm volatile("cp.async.wait_group 2;" ::: "memory")
// f32x2 packed FMA helpers
__device__ __forceinline__ unsigned long long pack2(float lo, float hi) {
    unsigned long long r;
    asm("mov.b64 %0, {%1, %2};" : "=l"(r) : "f"(lo), "f"(hi));
    return r;
}
__device__ __forceinline__ void unpack2(unsigned long long v, float& lo, float& hi) {
    asm("mov.b64 {%0, %1}, %2;" : "=f"(lo), "=f"(hi) : "l"(v));
}
__device__ __forceinline__ void fma2(unsigned long long& c, unsigned long long a,
                                     unsigned long long b) {
    asm("fma.rn.f32x2 %0, %1, %2, %0;" : "+l"(c) : "l"(a), "l"(b));
}

#define TSTRIDE 80                // 64B data + 16B pad (conflict-free ldmatrix)
#define TILESZ  (128 * TSTRIDE)   // 10240 bytes
#define APPROX_SMEM (4 * 2 * TILESZ + 2048)   // 4 stages x (A+B) + red
#define PROJ_SMEM   (2 * 4 * TILESZ)          // 2 stages x (Ahi,Alo,Bhi,Blo) = 80KB

// =====================================================================
// Merged convert kernel: x->fp16, W1->fp16, Wp->hi/lo
// =====================================================================
__global__ void __launch_bounds__(256)
conv_all_kernel(const float* __restrict__ x, const float* __restrict__ W1,
                const float* __restrict__ Wp) {
    const int bid = blockIdx.x, t = threadIdx.x;
    if (bid < TOK) {
        const size_t base = (size_t)bid * D_ + 4 * t;
        const float4 v = *(const float4*)(x + base);
        const __half2 h0 = __floats2half2_rn(v.x, v.y), h1 = __floats2half2_rn(v.z, v.w);
        *(uint2*)&g_xh[base] = make_uint2(*(const uint32_t*)&h0, *(const uint32_t*)&h1);
    } else if (bid < TOK + H_) {
        const size_t base = (size_t)(bid - TOK) * D_ + 4 * t;
        const float4 v = *(const float4*)(W1 + base);
        const __half2 h0 = __floats2half2_rn(v.x, v.y), h1 = __floats2half2_rn(v.z, v.w);
        *(uint2*)&g_w1h[base] = make_uint2(*(const uint32_t*)&h0, *(const uint32_t*)&h1);
    } else {
        const size_t base = (size_t)(bid - TOK - H_) * D_ + 4 * t;
        const float4 v = *(const float4*)(Wp + base);
        const __half2 h0 = __floats2half2_rn(v.x, v.y), h1 = __floats2half2_rn(v.z, v.w);
        const float2 f0 = __half22float2(h0), f1 = __half22float2(h1);
        const __half2 l0 = __floats2half2_rn(v.x - f0.x, v.y - f0.y);
        const __half2 l1 = __floats2half2_rn(v.z - f1.x, v.w - f1.y);
        *(uint2*)&g_wphi[base] = make_uint2(*(const uint32_t*)&h0, *(const uint32_t*)&h1);
        *(uint2*)&g_wplo[base] = make_uint2(*(const uint32_t*)&l0, *(const uint32_t*)&l1);
    }
}

__global__ void __launch_bounds__(256)
gather_conv_kernel(const float* __restrict__ x) {
    const int r = blockIdx.x, t = threadIdx.x;
    const int b = r / KSEL;
    const int tok = g_topk[r];
    const float4 v = *(const float4*)(x + ((size_t)b * N_ + tok) * D_ + 4 * t);
    const __half2 h0 = __floats2half2_rn(v.x, v.y), h1 = __floats2half2_rn(v.z, v.w);
    const float2 f0 = __half22float2(h0), f1 = __half22float2(h1);
    const __half2 l0 = __floats2half2_rn(v.x - f0.x, v.y - f0.y);
    const __half2 l1 = __floats2half2_rn(v.z - f1.x, v.w - f1.y);
    *(uint2*)&g_xhi[(size_t)r * D_ + 4 * t] = make_uint2(*(const uint32_t*)&h0, *(const uint32_t*)&h1);
    *(uint2*)&g_xlo[(size_t)r * D_ + 4 * t] = make_uint2(*(const uint32_t*)&l0, *(const uint32_t*)&l1);
}

// =====================================================================
// Kernel 1: approx scores via fp16 HMMA, 4-stage cp.async pipeline
// grid (4 hq, 512 m-tiles), 256 thr
// =====================================================================
__global__ void __launch_bounds__(256)
approx_score_kernel(const float* __restrict__ b1, const float* __restrict__ W2) {
    extern __shared__ __align__(16) unsigned char dsm[];
    float* red = (float*)(dsm + 4 * 2 * TILESZ);   // [128][4]

    const int t = threadIdx.x, lane = t & 31, w = t >> 5;
    const int hq = blockIdx.x, m0 = blockIdx.y * 128;
    const int wm = w & 1, wn = w >> 1;
    const int lrow = t >> 1;
    const __half* Asrc = g_xh  + (size_t)(m0 + lrow) * D_ + (t & 1) * 16;
    const __half* Bsrc = g_w1h + (size_t)(hq * 128 + lrow) * D_ + (t & 1) * 16;
    const uint32_t smb   = smem_u32(dsm);
    const uint32_t stoff = (uint32_t)lrow * TSTRIDE + (t & 1) * 32;

    auto issue = [&](int c, int s) {
        const uint32_t d = smb + (uint32_t)s * 2 * TILESZ + stoff;
        cpa16(d,               Asrc + c * 32);
        cpa16(d + 16,          Asrc + c * 32 + 8);
        cpa16(d + TILESZ,      Bsrc + c * 32);
        cpa16(d + TILESZ + 16, Bsrc + c * 32 + 8);
    };
    issue(0, 0); CP_COMMIT();
    issue(1, 1); CP_COMMIT();
    issue(2, 2); CP_COMMIT();

    float c[4][4][4];
#pragma unroll
    for (int mi = 0; mi < 4; mi++)
#pragma unroll
        for (int nj = 0; nj < 4; nj++)
#pragma unroll
            for (int e = 0; e < 4; e++) c[mi][nj][e] = 0.0f;

    for (int j = 0; j < 32; j++) {
        CP_WAIT2();
        __syncthreads();
        const int slot = j & 3;
        const uint32_t Abase = smb + (uint32_t)slot * 2 * TILESZ;
        const uint32_t Bbase = Abase + TILESZ;
#pragma unroll
        for (int ks = 0; ks < 2; ks++) {
            const int k0h = ks * 16;
            uint32_t Af[4][4], Bf[2][4];
#pragma unroll
            for (int mi = 0; mi < 4; mi++)
                ldsm4(Af[mi], Abase + (uint32_t)(64 * wm + 16 * mi + (lane & 7) + 8 * ((lane >> 3) & 1)) * TSTRIDE
                              + (uint32_t)(k0h + 8 * (lane >> 4)) * 2);
#pragma unroll
            for (int np = 0; np < 2; np++)
                ldsm4(Bf[np], Bbase + (uint32_t)(32 * wn + 16 * np + (lane & 7) + 8 * (lane >> 4)) * TSTRIDE
                              + (uint32_t)(k0h + 8 * ((lane >> 3) & 1)) * 2);
#pragma unroll
            for (int mi = 0; mi < 4; mi++)
#pragma unroll
                for (int nj = 0; nj < 4; nj++)
                    mma16816(c[mi][nj], Af[mi], &Bf[nj >> 1][(nj & 1) * 2]);
        }
        if (j + 3 < 32) issue(j + 3, (j + 3) & 3);
        CP_COMMIT();
    }

    // epilogue: +b1, fast-gelu, .W2 -> per-row partial
    float pr[4][2];
#pragma unroll
    for (int mi = 0; mi < 4; mi++) { pr[mi][0] = 0.0f; pr[mi][1] = 0.0f; }
#pragma unroll
    for (int mi = 0; mi < 4; mi++)
#pragma unroll
        for (int nj = 0; nj < 4; nj++)
#pragma unroll
            for (int e = 0; e < 4; e++) {
                const int h = hq * 128 + 32 * wn + 8 * nj + 2 * (lane & 3) + (e & 1);
                const float v = c[mi][nj][e] + __ldg(&b1[h]);
                pr[mi][e >> 1] += gelu_fast(v) * __ldg(&W2[h]);
            }
    __syncthreads();
#pragma unroll
    for (int mi = 0; mi < 4; mi++)
#pragma unroll
        for (int rh = 0; rh < 2; rh++) {
            float p = pr[mi][rh];
            p += __shfl_xor_sync(0xffffffffu, p, 1);
            p += __shfl_xor_sync(0xffffffffu, p, 2);
            if ((lane & 3) == 0) red[(64 * wm + 16 * mi + (lane >> 2) + 8 * rh) * 4 + wn] = p;
        }
    __syncthreads();
    if (t < 128)
        g_part[hq * TOK + m0 + t] = red[t * 4 + 0] + red[t * 4 + 1] + red[t * 4 + 2] + red[t * 4 + 3];
}

// =====================================================================
// Kernel 2: per-batch radix-select threshold at rank 256, compact candidates
// =====================================================================
__global__ void __launch_bounds__(256)
radix_cand_kernel() {
    __shared__ uint32_t key[N_];
    __shared__ int hist[256];
    __shared__ uint32_t s_prefix;
    __shared__ int s_remaining, s_cnt;
    const int b = blockIdx.x, t = threadIdx.x;

    for (int i = t; i < N_; i += 256) {
        const int g = b * N_ + i;
        const float s = g_part[g] + g_part[TOK + g] + g_part[2 * TOK + g] + g_part[3 * TOK + g];
        const uint32_t u = __float_as_uint(s);
        key[i] = (u & 0x80000000u) ? ~u : (u | 0x80000000u);
    }
    if (t == 0) { s_prefix = 0; s_remaining = 256; s_cnt = 0; }
    __syncthreads();

    for (int pass = 0; pass < 3; pass++) {
        const int shift = 24 - pass * 8;
        hist[t & 255] = 0;
        __syncthreads();
        const uint32_t pref = s_prefix;
        for (int i = t; i < N_; i += 256) {
            const uint32_t k = key[i];
            const bool match = (pass == 0) || ((k >> (shift + 8)) == pref);
            if (match) atomicAdd(&hist[(k >> shift) & 255], 1);
        }
        __syncthreads();
        if (t == 0) {
            int rem = s_remaining, acc = 0, v = 255;
            for (; v > 0; v--) { if (acc + hist[v] >= rem) break; acc += hist[v]; }
            s_prefix = (pref << 8) | (uint32_t)v;
            s_remaining = rem - acc;
        }
        __syncthreads();
    }

    const uint32_t thr = s_prefix;
    for (int i = t; i < N_; i += 256) {
        if ((key[i] >> 8) >= thr) {
            const int pos = atomicAdd(&s_cnt, 1);
            if (pos < CMAX) g_cand[b * CMAX + pos] = i;
        }
    }
    __syncthreads();
    const int cnt = min(s_cnt, CMAX);
    if (t == 0) g_ccount[b] = cnt;
    for (int i = cnt + t; i < CMAX; i += 256) g_cand[b * CMAX + i] = 0;
}

// =====================================================================
// Kernel 3: exact fp32 rescoring, 64 cand x 128 h per CTA
// thread = 2 cand x 16 h; B staged [k][h] for broadcast + conflict-free reads
// grid (CT64, 4, B_)
// =====================================================================
#define BSTRIDE 136   // floats per Bs row (128 data + 8 pad; 544B, 16B-aligned)
#define ASTRIDE 36
__global__ void __launch_bounds__(256)
exact_score_kernel(const float* __restrict__ x, const float* __restrict__ W1,
                   const float* __restrict__ b1, const float* __restrict__ W2) {
    const int ct = blockIdx.x, hq = blockIdx.y, b = blockIdx.z;
    if (ct * 64 >= g_ccount[b]) return;

    __shared__ __align__(16) float As[64][ASTRIDE];   // [cand][k]
    __shared__ __align__(16) float Bs[32][BSTRIDE];   // [k][h]
    __shared__ int cidx[64];
    const int t = threadIdx.x, lane = t & 31, w = t >> 5;
    if (t < 64) cidx[t] = g_cand[b * CMAX + ct * 64 + t];
    __syncthreads();

    const int tcol = lane & 7;          // h-group (16 h, strided by 32)
    const int trl  = lane >> 3;         // 0..3
    const int cb   = w * 8 + trl * 2;   // this thread's candidate pair base

    // loaders
    const int arow = t >> 2, acol = (t & 3) * 8;
    const int bh   = t >> 1, bks = (t & 1) * 16;
    const float* Agr = x  + ((size_t)b * N_ + cidx[arow]) * D_ + acol;
    const float* Bgr = W1 + (size_t)(hq * 128 + bh) * D_ + bks;

    unsigned long long acc0[4][2], acc1[4][2];
#pragma unroll
    for (int q = 0; q < 4; q++) {
        acc0[q][0] = pack2(0.0f, 0.0f); acc0[q][1] = pack2(0.0f, 0.0f);
        acc1[q][0] = pack2(0.0f, 0.0f); acc1[q][1] = pack2(0.0f, 0.0f);
    }

    for (int k0 = 0; k0 < D_; k0 += 32) {
        const float4 a0 = *(const float4*)(Agr + k0);
        const float4 a1 = *(const float4*)(Agr + k0 + 4);
        float4 bw[4];
#pragma unroll
        for (int q = 0; q < 4; q++) bw[q] = *(const float4*)(Bgr + k0 + 4 * q);
        __syncthreads();
        *(float4*)&As[arow][acol]     = a0;
        *(float4*)&As[arow][acol + 4] = a1;
#pragma unroll
        for (int q = 0; q < 4; q++) {
            Bs[bks + 4 * q + 0][bh] = bw[q].x;
            Bs[bks + 4 * q + 1][bh] = bw[q].y;
            Bs[bks + 4 * q + 2][bh] = bw[q].z;
            Bs[bks + 4 * q + 3][bh] = bw[q].w;
        }
        __syncthreads();
#pragma unroll
        for (int kk = 0; kk < 32; kk++) {
            const float v0 = As[cb][kk], v1 = As[cb + 1][kk];
            const unsigned long long aa0 = pack2(v0, v0);
            const unsigned long long aa1 = pack2(v1, v1);
#pragma unroll
            for (int q = 0; q < 4; q++) {
                const unsigned long long* brow =
                    (const unsigned long long*)&Bs[kk][tcol * 4 + q * 32];
                fma2(acc0[q][0], aa0, brow[0]); fma2(acc0[q][1], aa0, brow[1]);
                fma2(acc1[q][0], aa1, brow[0]); fma2(acc1[q][1], aa1, brow[1]);
            }
        }
    }

    float p0 = 0.0f, p1 = 0.0f;
#pragma unroll
    for (int q = 0; q < 4; q++) {
#pragma unroll
        for (int u = 0; u < 2; u++) {
            float c0, c1, d0, d1;
            unpack2(acc0[q][u], c0, c1);
            unpack2(acc1[q][u], d0, d1);
            const int h = hq * 128 + q * 32 + tcol * 4 + 2 * u;
            const float bb0 = __ldg(&b1[h]),     ww0 = __ldg(&W2[h]);
            const float bb1 = __ldg(&b1[h + 1]), ww1 = __ldg(&W2[h + 1]);
            p0 += gelu_exact(c0 + bb0) * ww0 + gelu_exact(c1 + bb1) * ww1;
            p1 += gelu_exact(d0 + bb0) * ww0 + gelu_exact(d1 + bb1) * ww1;
        }
    }
    // reduce over the 8 tcol lanes (lanes trl*8 + 0..7)
#pragma unroll
    for (int off = 1; off < 8; off <<= 1) {
        p0 += __shfl_xor_sync(0xffffffffu, p0, off);
        p1 += __shfl_xor_sync(0xffffffffu, p1, off);
    }
    if (tcol == 0) {
        float* dst = &g_cpart[((hq * B_) + b) * CMAX + ct * 64 + cb];
        dst[0] = p0; dst[1] = p1;
    }
}

// =====================================================================
// Kernel 4: rank-by-counting final top-200 (fully parallel, deterministic)
// =====================================================================
__global__ void __launch_bounds__(256)
final_topk_kernel() {
    __shared__ float cs[CMAX];
    __shared__ int   cid[CMAX];
    const int b = blockIdx.x, t = threadIdx.x;
    const int cnt = g_ccount[b];

    for (int i = t; i < CMAX; i += 256) {
        if (i < cnt) {
            float s = 0.0f;
#pragma unroll
            for (int hq = 0; hq < 4; hq++) s += g_cpart[((hq * B_) + b) * CMAX + i];
            cs[i] = s; cid[i] = g_cand[b * CMAX + i];
        } else { cs[i] = -FLT_MAX; cid[i] = 0x7fffffff; }
    }
    __syncthreads();

    for (int i = t; i < CMAX; i += 256) {
        const float si = cs[i];
        const int idi = cid[i];
        if (idi == 0x7fffffff) continue;
        int rank = 0;
#pragma unroll 8
        for (int j = 0; j < CMAX; j++) {
            const float sj = cs[j];
            rank += (sj > si) || (sj == si && cid[j] < idi);
        }
        if (rank < KSEL) g_topk[b * KSEL + rank] = idi;
    }
}

// =====================================================================
// Kernel 5: projection, 2-stage cp.async pipeline, 2 CTAs/SM, 3-mma split
// grid (32 o-tiles, 25 row-tiles), 256 thr, 80KB dynamic smem
// =====================================================================
__global__ void __launch_bounds__(256, 2)
proj_kernel(const float* __restrict__ bp, float* __restrict__ out) {
    extern __shared__ __align__(16) unsigned char dsm[];   // [2][4][TILESZ]

    const int t = threadIdx.x, lane = t & 31, w = t >> 5;
    const int wm = w & 1, wn = w >> 1;
    const int o0 = blockIdx.x * 128, r0 = blockIdx.y * 128;
    const int lrow = t >> 1;

    const __half* Ahg = g_xhi  + (size_t)(r0 + lrow) * D_ + (t & 1) * 16;
    const __half* Alg = g_xlo  + (size_t)(r0 + lrow) * D_ + (t & 1) * 16;
    const __half* Bhg = g_wphi + (size_t)(o0 + lrow) * D_ + (t & 1) * 16;
    const __half* Blg = g_wplo + (size_t)(o0 + lrow) * D_ + (t & 1) * 16;
    const uint32_t smb   = smem_u32(dsm);
    const uint32_t stoff = (uint32_t)lrow * TSTRIDE + (t & 1) * 32;

    auto issue = [&](int c, int s) {
        const uint32_t d = smb + (uint32_t)s * 4 * TILESZ + stoff;
        cpa16(d,                   Ahg + c * 32);
        cpa16(d + 16,              Ahg + c * 32 + 8);
        cpa16(d + TILESZ,          Alg + c * 32);
        cpa16(d + TILESZ + 16,     Alg + c * 32 + 8);
        cpa16(d + 2 * TILESZ,      Bhg + c * 32);
        cpa16(d + 2 * TILESZ + 16, Bhg + c * 32 + 8);
        cpa16(d + 3 * TILESZ,      Blg + c * 32);
        cpa16(d + 3 * TILESZ + 16, Blg + c * 32 + 8);
    };
    issue(0, 0); CP_COMMIT();
    issue(1, 1); CP_COMMIT();

    float c[4][4][4];
#pragma unroll
    for (int mi = 0; mi < 4; mi++)
#pragma unroll
        for (int nj = 0; nj < 4; nj++)
#pragma unroll
            for (int e = 0; e < 4; e++) c[mi][nj][e] = 0.0f;

    for (int j = 0; j < 32; j++) {
        CP_WAIT1();
        __syncthreads();
        const int slot = j & 1;
        const uint32_t Ahi = smb + (uint32_t)slot * 4 * TILESZ;
        const uint32_t Alo = Ahi + TILESZ;
        const uint32_t Bhi = Ahi + 2 * TILESZ;
        const uint32_t Blo = Ahi + 3 * TILESZ;
        const uint32_t aoff = (uint32_t)(64 * wm + (lane & 7) + 8 * ((lane >> 3) & 1)) * TSTRIDE + (uint32_t)(8 * (lane >> 4)) * 2;
        const uint32_t boff = (uint32_t)(32 * wn + (lane & 7) + 8 * (lane >> 4)) * TSTRIDE + (uint32_t)(8 * ((lane >> 3) & 1)) * 2;
#pragma unroll
        for (int ks = 0; ks < 2; ks++) {
            const uint32_t kb = (uint32_t)(ks * 16) * 2;
            uint32_t Ah[4][4], Al[4][4], Bh[2][4], Bl[2][4];
#pragma unroll
            for (int mi = 0; mi < 4; mi++) {
                ldsm4(Ah[mi], Ahi + aoff + (uint32_t)(16 * mi) * TSTRIDE + kb);
                ldsm4(Al[mi], Alo + aoff + (uint32_t)(16 * mi) * TSTRIDE + kb);
            }
#pragma unroll
            for (int np = 0; np < 2; np++) {
                ldsm4(Bh[np], Bhi + boff + (uint32_t)(16 * np) * TSTRIDE + kb);
                ldsm4(Bl[np], Blo + boff + (uint32_t)(16 * np) * TSTRIDE + kb);
            }
#pragma unroll
            for (int mi = 0; mi < 4; mi++)
#pragma unroll
                for (int nj = 0; nj < 4; nj++) {
                    mma16816(c[mi][nj], Ah[mi], &Bh[nj >> 1][(nj & 1) * 2]);
                    mma16816(c[mi][nj], Ah[mi], &Bl[nj >> 1][(nj & 1) * 2]);
                    mma16816(c[mi][nj], Al[mi], &Bh[nj >> 1][(nj & 1) * 2]);
                }
        }
        __syncthreads();   // all warps done reading this slot before overwrite
        if (j + 2 < 32) issue(j + 2, slot);
        CP_COMMIT();
    }

#pragma unroll
    for (int mi = 0; mi < 4; mi++)
#pragma unroll
        for (int nj = 0; nj < 4; nj++)
#pragma unroll
            for (int rh = 0; rh < 2; rh++) {
                const int R  = r0 + 64 * wm + 16 * mi + (lane >> 2) + 8 * rh;
                const int oc = o0 + 32 * wn + 8 * nj + 2 * (lane & 3);
                float2 v;
                v.x = c[mi][nj][2 * rh + 0] + __ldg(&bp[oc]);
                v.y = c[mi][nj][2 * rh + 1] + __ldg(&bp[oc + 1]);
                *(float2*)(out + (size_t)R * O_ + oc) = v;
            }
}

// =====================================================================
// Entry point
// =====================================================================
extern "C" void kernel_launch(void* const* d_in, const int* in_sizes, int n_in,
                              void* d_out, int out_size) {
    (void)in_sizes; (void)n_in; (void)out_size;
    const float* x  = (const float*)d_in[0];
    const float* W1 = (const float*)d_in[1];
    const float* b1 = (const float*)d_in[2];
    const float* W2 = (const float*)d_in[3];
    // d_in[4] = b2: constant shift, irrelevant to topk ordering
    const float* Wp = (const float*)d_in[5];
    const float* bp = (const float*)d_in[6];
    float* out = (float*)d_out;

    cudaFuncSetAttribute(approx_score_kernel, cudaFuncAttributeMaxDynamicSharedMemorySize, APPROX_SMEM);
    cudaFuncSetAttribute(proj_kernel,         cudaFuncAttributeMaxDynamicSharedMemorySize, PROJ_SMEM);

    conv_all_kernel<<<TOK + H_ + O_, 256>>>(x, W1, Wp);
    approx_score_kernel<<<dim3(4, TOK / 128), 256, APPROX_SMEM>>>(b1, W2);
    radix_cand_kernel<<<B_, 256>>>();
    exact_score_kernel<<<dim3(CT64, 4, B_), 256>>>(x, W1, b1, W2);
    final_topk_kernel<<<B_, 256>>>();
    gather_conv_kernel<<<RTOT, 256>>>(x);
    proj_kernel<<<dim3(O_ / 128, RTOT / 128), 256, PROJ_SMEM>>>(bp, out);
}